// round 3
// baseline (speedup 1.0000x reference)
#include <cuda_runtime.h>
#include <math.h>

// Problem constants
#define Bv   128
#define Tn   128
#define Cn   256
#define Hn   4
#define Ln   6
#define Vn   10000
#define HSn  64
#define DFFn 1024
#define BT   (Bv*Tn)   // 16384 rows

// ---------------- scratch (device globals; no allocation allowed) ----------
__device__ float g_X  [BT*Cn];     // residual stream
__device__ float g_Hb [BT*Cn];     // layernorm output
__device__ float g_Q  [BT*Cn];
__device__ float g_K  [BT*Cn];
__device__ float g_V  [BT*Cn];
__device__ float g_Att[BT*Cn];
__device__ float g_FF [BT*DFFn];
__device__ float g_W  [Bv*Hn*Tn*Tn];   // attention probs, 33.5 MB

// ---------------- embedding ------------------------------------------------
__global__ void embed_k(const int* __restrict__ idx,
                        const float* __restrict__ tok,
                        const float* __restrict__ pos,
                        float* __restrict__ X)
{
    int bt = blockIdx.x;           // 0..BT-1
    int c  = threadIdx.x;          // 0..255
    int t  = bt % Tn;
    int id = idx[bt];
    X[bt*Cn + c] = tok[id*Cn + c] + pos[t*Cn + c];
}

// ---------------- layernorm ------------------------------------------------
__global__ void ln_k(const float* __restrict__ in, float* __restrict__ out,
                     const float* __restrict__ g, const float* __restrict__ b)
{
    int row = blockIdx.x;
    int c   = threadIdx.x;
    __shared__ float sbuf[256];
    float v = in[row*Cn + c];
    sbuf[c] = v; __syncthreads();
    #pragma unroll
    for (int s = 128; s > 0; s >>= 1) { if (c < s) sbuf[c] += sbuf[c+s]; __syncthreads(); }
    float mean = sbuf[0] * (1.0f/Cn);
    __syncthreads();
    float d = v - mean;
    sbuf[c] = d*d; __syncthreads();
    #pragma unroll
    for (int s = 128; s > 0; s >>= 1) { if (c < s) sbuf[c] += sbuf[c+s]; __syncthreads(); }
    float var = sbuf[0] * (1.0f/Cn);
    float r = rsqrtf(var + 1e-5f);
    out[row*Cn + c] = d * r * g[c] + b[c];
}

// ---------------- generic SGEMM: C = A[M,K] * B[K,N] (+bias +res +relu) ----
// BM=BN=128, BK=8, 256 threads, 8x8 microtile per thread.
// Software-pipelined: next K-slice prefetched into registers during compute.
// M must be a multiple of 128, K a multiple of 8. N can be ragged.
// EPI bit0 = +bias[n], bit1 = +res[m*ldc+n], bit2 = relu
template<int EPI>
__global__ void __launch_bounds__(256, 2)
sgemm_k(int M, int N, int K,
        const float* __restrict__ A, int lda,
        const float* __restrict__ B, int ldb,
        const float* __restrict__ bias,
        const float* __restrict__ res,
        float* __restrict__ C, int ldc)
{
    __shared__ float As[8][128];
    __shared__ float Bs[8][128];
    int tid = threadIdx.x;
    int tx = tid & 15, ty = tid >> 4;
    int bm = blockIdx.y * 128, bn = blockIdx.x * 128;

    float acc[8][8];
    #pragma unroll
    for (int i = 0; i < 8; i++)
        #pragma unroll
        for (int j = 0; j < 8; j++) acc[i][j] = 0.f;

    int arow = tid >> 1;            // 0..127
    int a4   = (tid & 1) * 4;       // 0 or 4
    int bk   = tid >> 5;            // 0..7
    int b4   = (tid & 31) * 4;      // 0..124
    bool bok = (bn + b4 < N);

    const float* Ap = A + (size_t)(bm + arow)*lda + a4;
    const float* Bp = B + (size_t)bk*ldb + bn + b4;

    // prologue: load first slice
    float4 av = *(const float4*)(Ap);
    float4 bv = bok ? *(const float4*)(Bp) : make_float4(0.f,0.f,0.f,0.f);

    for (int k0 = 0; k0 < K; k0 += 8) {
        As[a4+0][arow] = av.x; As[a4+1][arow] = av.y;
        As[a4+2][arow] = av.z; As[a4+3][arow] = av.w;
        *(float4*)&Bs[bk][b4] = bv;
        __syncthreads();

        // prefetch next slice while computing on this one
        if (k0 + 8 < K) {
            av = *(const float4*)(Ap + k0 + 8);
            bv = bok ? *(const float4*)(Bp + (size_t)8*ldb)
                     : make_float4(0.f,0.f,0.f,0.f);
            Bp += (size_t)8*ldb;
        }

        #pragma unroll
        for (int kk = 0; kk < 8; kk++) {
            float4 a0 = *(float4*)&As[kk][ty*4];
            float4 a1 = *(float4*)&As[kk][ty*4 + 64];
            float4 b0 = *(float4*)&Bs[kk][tx*4];
            float4 b1 = *(float4*)&Bs[kk][tx*4 + 64];
            float af[8] = {a0.x,a0.y,a0.z,a0.w,a1.x,a1.y,a1.z,a1.w};
            float bf[8] = {b0.x,b0.y,b0.z,b0.w,b1.x,b1.y,b1.z,b1.w};
            #pragma unroll
            for (int i = 0; i < 8; i++)
                #pragma unroll
                for (int j = 0; j < 8; j++)
                    acc[i][j] += af[i]*bf[j];
        }
        __syncthreads();
    }

    #pragma unroll
    for (int i = 0; i < 8; i++) {
        int m = bm + ((i < 4) ? (ty*4 + i) : (64 + ty*4 + i - 4));
        #pragma unroll
        for (int j = 0; j < 8; j++) {
            int n = bn + ((j < 4) ? (tx*4 + j) : (64 + tx*4 + j - 4));
            if (n < N) {
                float v = acc[i][j];
                if (EPI & 1) v += bias[n];
                if (EPI & 2) v += res[(size_t)m*ldc + n];
                if (EPI & 4) v = fmaxf(v, 0.f);
                C[(size_t)m*ldc + n] = v;
            }
        }
    }
}

// ---------------- attention scores: S[q,k] = scale * <Q_q, K_k> ------------
// one block per (b,h); 128x128 output, K-dim = 64 in chunks of 16
__global__ void __launch_bounds__(256, 2)
scores_k(const float* __restrict__ Q, const float* __restrict__ K,
         float* __restrict__ W)
{
    int bh = blockIdx.x;
    int b = bh >> 2, h = bh & 3;
    const float* Qp = Q + (size_t)b*Tn*Cn + h*HSn;
    const float* Kp = K + (size_t)b*Tn*Cn + h*HSn;
    float* Wp = W + (size_t)bh*Tn*Tn;

    __shared__ float Qs[16][128];
    __shared__ float Ks[16][128];
    int tid = threadIdx.x;
    int tx = tid & 15, ty = tid >> 4;

    float acc[8][8];
    #pragma unroll
    for (int i = 0; i < 8; i++)
        #pragma unroll
        for (int j = 0; j < 8; j++) acc[i][j] = 0.f;

    for (int d0 = 0; d0 < HSn; d0 += 16) {
        #pragma unroll
        for (int it = 0; it < 2; it++) {
            int v  = tid + it*256;       // 0..511
            int q  = v >> 2;             // 0..127
            int f4 = (v & 3) * 4;        // 0,4,8,12
            float4 qa = *(const float4*)(Qp + (size_t)q*Cn + d0 + f4);
            Qs[f4+0][q] = qa.x; Qs[f4+1][q] = qa.y;
            Qs[f4+2][q] = qa.z; Qs[f4+3][q] = qa.w;
            float4 ka = *(const float4*)(Kp + (size_t)q*Cn + d0 + f4);
            Ks[f4+0][q] = ka.x; Ks[f4+1][q] = ka.y;
            Ks[f4+2][q] = ka.z; Ks[f4+3][q] = ka.w;
        }
        __syncthreads();
        #pragma unroll
        for (int kk = 0; kk < 16; kk++) {
            float4 a0 = *(float4*)&Qs[kk][ty*4];
            float4 a1 = *(float4*)&Qs[kk][ty*4 + 64];
            float4 b0 = *(float4*)&Ks[kk][tx*4];
            float4 b1 = *(float4*)&Ks[kk][tx*4 + 64];
            float af[8] = {a0.x,a0.y,a0.z,a0.w,a1.x,a1.y,a1.z,a1.w};
            float bf[8] = {b0.x,b0.y,b0.z,b0.w,b1.x,b1.y,b1.z,b1.w};
            #pragma unroll
            for (int i = 0; i < 8; i++)
                #pragma unroll
                for (int j = 0; j < 8; j++)
                    acc[i][j] += af[i]*bf[j];
        }
        __syncthreads();
    }

    const float scale = 0.0625f;   // C^-0.5 = 1/sqrt(256)
    #pragma unroll
    for (int i = 0; i < 8; i++) {
        int q = (i < 4) ? (ty*4 + i) : (64 + ty*4 + i - 4);
        #pragma unroll
        for (int j = 0; j < 8; j++) {
            int k = (j < 4) ? (tx*4 + j) : (64 + tx*4 + j - 4);
            Wp[q*Tn + k] = acc[i][j] * scale;
        }
    }
}

// ---------------- causal softmax over rows of W (length 128) ---------------
__global__ void softmax_k(float* __restrict__ W)
{
    int row  = blockIdx.x * 8 + (threadIdx.x >> 5);
    int lane = threadIdx.x & 31;
    int q = row % Tn;
    float* p = W + (size_t)row*Tn;

    float4 v = *(float4*)(p + lane*4);
    float vals[4] = {v.x, v.y, v.z, v.w};
    float mx = -1e30f;
    #pragma unroll
    for (int i = 0; i < 4; i++) {
        int k = lane*4 + i;
        if (k > q) vals[i] = -1e30f;
        mx = fmaxf(mx, vals[i]);
    }
    #pragma unroll
    for (int s = 16; s > 0; s >>= 1)
        mx = fmaxf(mx, __shfl_xor_sync(0xFFFFFFFF, mx, s));
    float sum = 0.f;
    #pragma unroll
    for (int i = 0; i < 4; i++) {
        int k = lane*4 + i;
        vals[i] = (k > q) ? 0.f : __expf(vals[i] - mx);
        sum += vals[i];
    }
    #pragma unroll
    for (int s = 16; s > 0; s >>= 1)
        sum += __shfl_xor_sync(0xFFFFFFFF, sum, s);
    float inv = 1.f / sum;
    *(float4*)(p + lane*4) = make_float4(vals[0]*inv, vals[1]*inv, vals[2]*inv, vals[3]*inv);
}

// ---------------- AV: O[q,d] = sum_k P[q,k] V[k,d] -------------------------
// one block per (b,h); output 128x64, K-dim = 128 in chunks of 16
__global__ void __launch_bounds__(256, 2)
av_k(const float* __restrict__ W, const float* __restrict__ V,
     float* __restrict__ Att)
{
    int bh = blockIdx.x;
    int b = bh >> 2, h = bh & 3;
    const float* Wp = W + (size_t)bh*Tn*Tn;
    const float* Vp = V + (size_t)b*Tn*Cn + h*HSn;
    float* Op = Att + (size_t)b*Tn*Cn + h*HSn;

    __shared__ float Ps[16][128];
    __shared__ float Vs[16][64];
    int tid = threadIdx.x;
    int tx = tid & 15, ty = tid >> 4;

    float acc[8][4];
    #pragma unroll
    for (int i = 0; i < 8; i++)
        #pragma unroll
        for (int j = 0; j < 4; j++) acc[i][j] = 0.f;

    for (int k0 = 0; k0 < Tn; k0 += 16) {
        #pragma unroll
        for (int it = 0; it < 2; it++) {
            int v  = tid + it*256;
            int q  = v >> 2;
            int f4 = (v & 3) * 4;
            float4 pa = *(const float4*)(Wp + (size_t)q*Tn + k0 + f4);
            Ps[f4+0][q] = pa.x; Ps[f4+1][q] = pa.y;
            Ps[f4+2][q] = pa.z; Ps[f4+3][q] = pa.w;
        }
        {
            int kk = tid >> 4;            // 0..15
            int d4 = (tid & 15) * 4;      // 0..60
            float4 va = *(const float4*)(Vp + (size_t)(k0 + kk)*Cn + d4);
            *(float4*)&Vs[kk][d4] = va;
        }
        __syncthreads();
        #pragma unroll
        for (int kk = 0; kk < 16; kk++) {
            float4 a0 = *(float4*)&Ps[kk][ty*4];
            float4 a1 = *(float4*)&Ps[kk][ty*4 + 64];
            float4 b0 = *(float4*)&Vs[kk][tx*4];
            float af[8] = {a0.x,a0.y,a0.z,a0.w,a1.x,a1.y,a1.z,a1.w};
            float bf[4] = {b0.x,b0.y,b0.z,b0.w};
            #pragma unroll
            for (int i = 0; i < 8; i++)
                #pragma unroll
                for (int j = 0; j < 4; j++)
                    acc[i][j] += af[i]*bf[j];
        }
        __syncthreads();
    }

    #pragma unroll
    for (int i = 0; i < 8; i++) {
        int q = (i < 4) ? (ty*4 + i) : (64 + ty*4 + i - 4);
        #pragma unroll
        for (int j = 0; j < 4; j++) {
            int d = tx*4 + j;
            Op[(size_t)q*Cn + d] = acc[i][j];
        }
    }
}

// ---------------- host launcher --------------------------------------------
extern "C" void kernel_launch(void* const* d_in, const int* in_sizes, int n_in,
                              void* d_out, int out_size)
{
    const int*   idx    = (const int*)  d_in[0];
    const float* tok    = (const float*)d_in[1];
    const float* pos    = (const float*)d_in[2];
    const float* ln1_g  = (const float*)d_in[3];
    const float* ln1_b  = (const float*)d_in[4];
    const float* wq     = (const float*)d_in[5];
    const float* wk     = (const float*)d_in[6];
    const float* wv     = (const float*)d_in[7];
    const float* proj_w = (const float*)d_in[8];
    const float* proj_b = (const float*)d_in[9];
    const float* ln2_g  = (const float*)d_in[10];
    const float* ln2_b  = (const float*)d_in[11];
    const float* w1     = (const float*)d_in[12];
    const float* b1     = (const float*)d_in[13];
    const float* w2     = (const float*)d_in[14];
    const float* b2     = (const float*)d_in[15];
    const float* lnf_g  = (const float*)d_in[16];
    const float* lnf_b  = (const float*)d_in[17];
    const float* lm_w   = (const float*)d_in[18];
    const float* lm_b   = (const float*)d_in[19];
    float* out = (float*)d_out;

    float *X, *Hb, *Q, *K, *V, *Att, *FF, *W;
    cudaGetSymbolAddress((void**)&X,   g_X);
    cudaGetSymbolAddress((void**)&Hb,  g_Hb);
    cudaGetSymbolAddress((void**)&Q,   g_Q);
    cudaGetSymbolAddress((void**)&K,   g_K);
    cudaGetSymbolAddress((void**)&V,   g_V);
    cudaGetSymbolAddress((void**)&Att, g_Att);
    cudaGetSymbolAddress((void**)&FF,  g_FF);
    cudaGetSymbolAddress((void**)&W,   g_W);

    embed_k<<<BT, 256>>>(idx, tok, pos, X);

    dim3 gC(Cn/128, BT/128);      // N=256
    dim3 gF(DFFn/128, BT/128);    // N=1024
    dim3 gV((Vn + 127)/128, BT/128);

    for (int l = 0; l < Ln; l++) {
        ln_k<<<BT, 256>>>(X, Hb, ln1_g + l*Cn, ln1_b + l*Cn);

        sgemm_k<0><<<gC, 256>>>(BT, Cn, Cn, Hb, Cn, wq + (size_t)l*Cn*Cn, Cn,
                                nullptr, nullptr, Q, Cn);
        sgemm_k<0><<<gC, 256>>>(BT, Cn, Cn, Hb, Cn, wk + (size_t)l*Cn*Cn, Cn,
                                nullptr, nullptr, K, Cn);
        sgemm_k<0><<<gC, 256>>>(BT, Cn, Cn, Hb, Cn, wv + (size_t)l*Cn*Cn, Cn,
                                nullptr, nullptr, V, Cn);

        scores_k<<<Bv*Hn, 256>>>(Q, K, W);
        softmax_k<<<Bv*Hn*Tn/8, 256>>>(W);
        av_k<<<Bv*Hn, 256>>>(W, V, Att);

        // x = x + att @ proj_w + proj_b
        sgemm_k<3><<<gC, 256>>>(BT, Cn, Cn, Att, Cn, proj_w + (size_t)l*Cn*Cn, Cn,
                                proj_b + l*Cn, X, X, Cn);

        ln_k<<<BT, 256>>>(X, Hb, ln2_g + l*Cn, ln2_b + l*Cn);

        // ff = relu(h2 @ w1 + b1)
        sgemm_k<5><<<gF, 256>>>(BT, DFFn, Cn, Hb, Cn, w1 + (size_t)l*Cn*DFFn, DFFn,
                                b1 + l*DFFn, nullptr, FF, DFFn);
        // x = x + ff @ w2 + b2
        sgemm_k<3><<<gC, 256>>>(BT, Cn, DFFn, FF, DFFn, w2 + (size_t)l*DFFn*Cn, Cn,
                                b2 + l*Cn, X, X, Cn);
    }

    ln_k<<<BT, 256>>>(X, Hb, lnf_g, lnf_b);
    sgemm_k<1><<<gV, 256>>>(BT, Vn, Cn, Hb, Cn, lm_w, Vn,
                            lm_b, nullptr, out, Vn);
}

// round 4
// speedup vs baseline: 1.5905x; 1.5905x over previous
#include <cuda_runtime.h>
#include <math.h>

// Problem constants
#define Bv   128
#define Tn   128
#define Cn   256
#define Hn   4
#define Ln   6
#define Vn   10000
#define HSn  64
#define DFFn 1024
#define BT   (Bv*Tn)   // 16384 rows

// ---------------- scratch (device globals; no allocation allowed) ----------
__device__ float g_X  [BT*Cn];     // residual stream
__device__ float g_Hb [BT*Cn];     // layernorm output
__device__ float g_Q  [BT*Cn];
__device__ float g_K  [BT*Cn];
__device__ float g_V  [BT*Cn];
__device__ float g_Att[BT*Cn];
__device__ float g_FF [BT*DFFn];
__device__ float g_W  [Bv*Hn*Tn*Tn];   // attention probs, 33.5 MB

// ---------------- helpers ---------------------------------------------------
__device__ __forceinline__ unsigned f2tf32(float x) {
    unsigned r;
    asm("cvt.rna.tf32.f32 %0, %1;" : "=r"(r) : "f"(x));
    return r;
}

__device__ __forceinline__ void mma_tf32(float* c, const unsigned* a, const unsigned* b) {
    asm volatile(
        "mma.sync.aligned.m16n8k8.row.col.f32.tf32.tf32.f32 "
        "{%0,%1,%2,%3}, {%4,%5,%6,%7}, {%8,%9}, {%0,%1,%2,%3};"
        : "+f"(c[0]), "+f"(c[1]), "+f"(c[2]), "+f"(c[3])
        : "r"(a[0]), "r"(a[1]), "r"(a[2]), "r"(a[3]), "r"(b[0]), "r"(b[1]));
}

// ---------------- embedding ------------------------------------------------
__global__ void embed_k(const int* __restrict__ idx,
                        const float* __restrict__ tok,
                        const float* __restrict__ pos,
                        float* __restrict__ X)
{
    int bt = blockIdx.x;
    int c  = threadIdx.x;
    int t  = bt % Tn;
    int id = idx[bt];
    X[bt*Cn + c] = tok[id*Cn + c] + pos[t*Cn + c];
}

// ---------------- layernorm ------------------------------------------------
__global__ void ln_k(const float* __restrict__ in, float* __restrict__ out,
                     const float* __restrict__ g, const float* __restrict__ b)
{
    int row = blockIdx.x;
    int c   = threadIdx.x;
    __shared__ float sbuf[256];
    float v = in[row*Cn + c];
    sbuf[c] = v; __syncthreads();
    #pragma unroll
    for (int s = 128; s > 0; s >>= 1) { if (c < s) sbuf[c] += sbuf[c+s]; __syncthreads(); }
    float mean = sbuf[0] * (1.0f/Cn);
    __syncthreads();
    float d = v - mean;
    sbuf[c] = d*d; __syncthreads();
    #pragma unroll
    for (int s = 128; s > 0; s >>= 1) { if (c < s) sbuf[c] += sbuf[c+s]; __syncthreads(); }
    float var = sbuf[0] * (1.0f/Cn);
    float r = rsqrtf(var + 1e-5f);
    out[row*Cn + c] = d * r * g[c] + b[c];
}

// ---------------- TF32 tensor-core GEMM: C = A[M,K] * B[K,N] ----------------
// BM=BN=128, BK=16, 256 threads = 8 warps, warp tile 32x64
// (warp grid 4x2: wm = (wid&3)*32, wn = (wid>>2)*64)
// EPI bit0 = +bias[n], bit1 = +res[m*ldc+n], bit2 = relu
// M % 128 == 0, K % 16 == 0, N ragged OK (N % 4 == 0).
template<int EPI>
__global__ void __launch_bounds__(256, 2)
tcgemm_k(int M, int N, int K,
         const float* __restrict__ A, int lda,
         const float* __restrict__ B, int ldb,
         const float* __restrict__ bias,
         const float* __restrict__ res,
         float* __restrict__ C, int ldc)
{
    __shared__ unsigned As[128][17];   // [m][k], pad 17 -> conflict-free frags
    __shared__ unsigned Bs[16][136];   // [k][n], pad 136 -> conflict-free frags

    int tid  = threadIdx.x;
    int wid  = tid >> 5, lane = tid & 31;
    int grp  = lane >> 2, tg = lane & 3;
    int wm   = (wid & 3) * 32;
    int wn   = (wid >> 2) * 64;
    int bm   = blockIdx.y * 128, bn = blockIdx.x * 128;

    float acc[2][8][4];
    #pragma unroll
    for (int mt = 0; mt < 2; mt++)
        #pragma unroll
        for (int nt = 0; nt < 8; nt++)
            #pragma unroll
            for (int r = 0; r < 4; r++) acc[mt][nt][r] = 0.f;

    // gmem staging indices
    int arow = tid >> 1;                 // 0..127
    int akc  = (tid & 1) * 4;            // 0 or 4  (+8 for it=1)
    int brow = tid >> 4;                 // 0..15
    int bnc  = (tid & 15) * 4;           // 0..60   (+64 for it=1)
    const float* Ap = A + (size_t)(bm + arow)*lda + akc;
    const float* Bp = B + (size_t)brow*ldb + bn + bnc;
    bool bok0 = (bn + bnc      < N);
    bool bok1 = (bn + bnc + 64 < N);

    float4 pa0, pa1, pb0, pb1;
    // prologue loads (k0 = 0)
    pa0 = *(const float4*)(Ap);
    pa1 = *(const float4*)(Ap + 8);
    pb0 = bok0 ? *(const float4*)(Bp)      : make_float4(0.f,0.f,0.f,0.f);
    pb1 = bok1 ? *(const float4*)(Bp + 64) : make_float4(0.f,0.f,0.f,0.f);

    for (int k0 = 0; k0 < K; k0 += 16) {
        // store staged regs -> smem (cvt to tf32, RNA)
        As[arow][akc+0] = f2tf32(pa0.x); As[arow][akc+1] = f2tf32(pa0.y);
        As[arow][akc+2] = f2tf32(pa0.z); As[arow][akc+3] = f2tf32(pa0.w);
        As[arow][akc+8] = f2tf32(pa1.x); As[arow][akc+9] = f2tf32(pa1.y);
        As[arow][akc+10]= f2tf32(pa1.z); As[arow][akc+11]= f2tf32(pa1.w);
        Bs[brow][bnc+0] = f2tf32(pb0.x); Bs[brow][bnc+1] = f2tf32(pb0.y);
        Bs[brow][bnc+2] = f2tf32(pb0.z); Bs[brow][bnc+3] = f2tf32(pb0.w);
        Bs[brow][bnc+64]= f2tf32(pb1.x); Bs[brow][bnc+65]= f2tf32(pb1.y);
        Bs[brow][bnc+66]= f2tf32(pb1.z); Bs[brow][bnc+67]= f2tf32(pb1.w);
        __syncthreads();

        // prefetch next slice (latency hidden by MMA section below)
        if (k0 + 16 < K) {
            pa0 = *(const float4*)(Ap + k0 + 16);
            pa1 = *(const float4*)(Ap + k0 + 24);
            Bp += (size_t)16*ldb;
            pb0 = bok0 ? *(const float4*)(Bp)      : make_float4(0.f,0.f,0.f,0.f);
            pb1 = bok1 ? *(const float4*)(Bp + 64) : make_float4(0.f,0.f,0.f,0.f);
        }

        #pragma unroll
        for (int ks = 0; ks < 2; ks++) {
            int k = ks*8;
            unsigned bfr[8][2];
            #pragma unroll
            for (int nt = 0; nt < 8; nt++) {
                bfr[nt][0] = Bs[k+tg  ][wn + nt*8 + grp];
                bfr[nt][1] = Bs[k+tg+4][wn + nt*8 + grp];
            }
            #pragma unroll
            for (int mt = 0; mt < 2; mt++) {
                unsigned afr[4];
                afr[0] = As[wm + mt*16 + grp    ][k + tg    ];
                afr[1] = As[wm + mt*16 + grp + 8][k + tg    ];
                afr[2] = As[wm + mt*16 + grp    ][k + tg + 4];
                afr[3] = As[wm + mt*16 + grp + 8][k + tg + 4];
                #pragma unroll
                for (int nt = 0; nt < 8; nt++)
                    mma_tf32(acc[mt][nt], afr, bfr[nt]);
            }
        }
        __syncthreads();
    }

    // epilogue: c0 (r,c), c1 (r,c+1), c2 (r+8,c), c3 (r+8,c+1)
    #pragma unroll
    for (int mt = 0; mt < 2; mt++) {
        int r0 = bm + wm + mt*16 + grp;
        #pragma unroll
        for (int nt = 0; nt < 8; nt++) {
            int c0 = bn + wn + nt*8 + 2*tg;
            #pragma unroll
            for (int half = 0; half < 2; half++) {
                int r = r0 + half*8;
                float v0 = acc[mt][nt][half*2+0];
                float v1 = acc[mt][nt][half*2+1];
                if (c0 < N) {
                    if (EPI & 1) v0 += bias[c0];
                    if (EPI & 2) v0 += res[(size_t)r*ldc + c0];
                    if (EPI & 4) v0 = fmaxf(v0, 0.f);
                    C[(size_t)r*ldc + c0] = v0;
                }
                if (c0 + 1 < N) {
                    if (EPI & 1) v1 += bias[c0+1];
                    if (EPI & 2) v1 += res[(size_t)r*ldc + c0+1];
                    if (EPI & 4) v1 = fmaxf(v1, 0.f);
                    C[(size_t)r*ldc + c0+1] = v1;
                }
            }
        }
    }
}

// ---------------- attention scores: S[q,k] = scale * <Q_q, K_k> ------------
__global__ void __launch_bounds__(256, 2)
scores_k(const float* __restrict__ Q, const float* __restrict__ K,
         float* __restrict__ W)
{
    int bh = blockIdx.x;
    int b = bh >> 2, h = bh & 3;
    const float* Qp = Q + (size_t)b*Tn*Cn + h*HSn;
    const float* Kp = K + (size_t)b*Tn*Cn + h*HSn;
    float* Wp = W + (size_t)bh*Tn*Tn;

    __shared__ float Qs[16][128];
    __shared__ float Ks[16][128];
    int tid = threadIdx.x;
    int tx = tid & 15, ty = tid >> 4;

    float acc[8][8];
    #pragma unroll
    for (int i = 0; i < 8; i++)
        #pragma unroll
        for (int j = 0; j < 8; j++) acc[i][j] = 0.f;

    for (int d0 = 0; d0 < HSn; d0 += 16) {
        #pragma unroll
        for (int it = 0; it < 2; it++) {
            int v  = tid + it*256;
            int q  = v >> 2;
            int f4 = (v & 3) * 4;
            float4 qa = *(const float4*)(Qp + (size_t)q*Cn + d0 + f4);
            Qs[f4+0][q] = qa.x; Qs[f4+1][q] = qa.y;
            Qs[f4+2][q] = qa.z; Qs[f4+3][q] = qa.w;
            float4 ka = *(const float4*)(Kp + (size_t)q*Cn + d0 + f4);
            Ks[f4+0][q] = ka.x; Ks[f4+1][q] = ka.y;
            Ks[f4+2][q] = ka.z; Ks[f4+3][q] = ka.w;
        }
        __syncthreads();
        #pragma unroll
        for (int kk = 0; kk < 16; kk++) {
            float4 a0 = *(float4*)&Qs[kk][ty*4];
            float4 a1 = *(float4*)&Qs[kk][ty*4 + 64];
            float4 b0 = *(float4*)&Ks[kk][tx*4];
            float4 b1 = *(float4*)&Ks[kk][tx*4 + 64];
            float af[8] = {a0.x,a0.y,a0.z,a0.w,a1.x,a1.y,a1.z,a1.w};
            float bf[8] = {b0.x,b0.y,b0.z,b0.w,b1.x,b1.y,b1.z,b1.w};
            #pragma unroll
            for (int i = 0; i < 8; i++)
                #pragma unroll
                for (int j = 0; j < 8; j++)
                    acc[i][j] += af[i]*bf[j];
        }
        __syncthreads();
    }

    const float scale = 0.0625f;   // 1/sqrt(256)
    #pragma unroll
    for (int i = 0; i < 8; i++) {
        int q = (i < 4) ? (ty*4 + i) : (64 + ty*4 + i - 4);
        #pragma unroll
        for (int j = 0; j < 8; j++) {
            int k = (j < 4) ? (tx*4 + j) : (64 + tx*4 + j - 4);
            Wp[q*Tn + k] = acc[i][j] * scale;
        }
    }
}

// ---------------- causal softmax over rows of W (length 128) ---------------
__global__ void softmax_k(float* __restrict__ W)
{
    int row  = blockIdx.x * 8 + (threadIdx.x >> 5);
    int lane = threadIdx.x & 31;
    int q = row % Tn;
    float* p = W + (size_t)row*Tn;

    float4 v = *(float4*)(p + lane*4);
    float vals[4] = {v.x, v.y, v.z, v.w};
    float mx = -1e30f;
    #pragma unroll
    for (int i = 0; i < 4; i++) {
        int k = lane*4 + i;
        if (k > q) vals[i] = -1e30f;
        mx = fmaxf(mx, vals[i]);
    }
    #pragma unroll
    for (int s = 16; s > 0; s >>= 1)
        mx = fmaxf(mx, __shfl_xor_sync(0xFFFFFFFF, mx, s));
    float sum = 0.f;
    #pragma unroll
    for (int i = 0; i < 4; i++) {
        int k = lane*4 + i;
        vals[i] = (k > q) ? 0.f : __expf(vals[i] - mx);
        sum += vals[i];
    }
    #pragma unroll
    for (int s = 16; s > 0; s >>= 1)
        sum += __shfl_xor_sync(0xFFFFFFFF, sum, s);
    float inv = 1.f / sum;
    *(float4*)(p + lane*4) = make_float4(vals[0]*inv, vals[1]*inv, vals[2]*inv, vals[3]*inv);
}

// ---------------- AV: O[q,d] = sum_k P[q,k] V[k,d] -------------------------
__global__ void __launch_bounds__(256, 2)
av_k(const float* __restrict__ W, const float* __restrict__ V,
     float* __restrict__ Att)
{
    int bh = blockIdx.x;
    int b = bh >> 2, h = bh & 3;
    const float* Wp = W + (size_t)bh*Tn*Tn;
    const float* Vp = V + (size_t)b*Tn*Cn + h*HSn;
    float* Op = Att + (size_t)b*Tn*Cn + h*HSn;

    __shared__ float Ps[16][128];
    __shared__ float Vs[16][64];
    int tid = threadIdx.x;
    int tx = tid & 15, ty = tid >> 4;

    float acc[8][4];
    #pragma unroll
    for (int i = 0; i < 8; i++)
        #pragma unroll
        for (int j = 0; j < 4; j++) acc[i][j] = 0.f;

    for (int k0 = 0; k0 < Tn; k0 += 16) {
        #pragma unroll
        for (int it = 0; it < 2; it++) {
            int v  = tid + it*256;
            int q  = v >> 2;
            int f4 = (v & 3) * 4;
            float4 pa = *(const float4*)(Wp + (size_t)q*Tn + k0 + f4);
            Ps[f4+0][q] = pa.x; Ps[f4+1][q] = pa.y;
            Ps[f4+2][q] = pa.z; Ps[f4+3][q] = pa.w;
        }
        {
            int kk = tid >> 4;
            int d4 = (tid & 15) * 4;
            float4 va = *(const float4*)(Vp + (size_t)(k0 + kk)*Cn + d4);
            *(float4*)&Vs[kk][d4] = va;
        }
        __syncthreads();
        #pragma unroll
        for (int kk = 0; kk < 16; kk++) {
            float4 a0 = *(float4*)&Ps[kk][ty*4];
            float4 a1 = *(float4*)&Ps[kk][ty*4 + 64];
            float4 b0 = *(float4*)&Vs[kk][tx*4];
            float af[8] = {a0.x,a0.y,a0.z,a0.w,a1.x,a1.y,a1.z,a1.w};
            float bf[4] = {b0.x,b0.y,b0.z,b0.w};
            #pragma unroll
            for (int i = 0; i < 8; i++)
                #pragma unroll
                for (int j = 0; j < 4; j++)
                    acc[i][j] += af[i]*bf[j];
        }
        __syncthreads();
    }

    #pragma unroll
    for (int i = 0; i < 8; i++) {
        int q = (i < 4) ? (ty*4 + i) : (64 + ty*4 + i - 4);
        #pragma unroll
        for (int j = 0; j < 4; j++) {
            int d = tx*4 + j;
            Op[(size_t)q*Cn + d] = acc[i][j];
        }
    }
}

// ---------------- host launcher --------------------------------------------
extern "C" void kernel_launch(void* const* d_in, const int* in_sizes, int n_in,
                              void* d_out, int out_size)
{
    const int*   idx    = (const int*)  d_in[0];
    const float* tok    = (const float*)d_in[1];
    const float* pos    = (const float*)d_in[2];
    const float* ln1_g  = (const float*)d_in[3];
    const float* ln1_b  = (const float*)d_in[4];
    const float* wq     = (const float*)d_in[5];
    const float* wk     = (const float*)d_in[6];
    const float* wv     = (const float*)d_in[7];
    const float* proj_w = (const float*)d_in[8];
    const float* proj_b = (const float*)d_in[9];
    const float* ln2_g  = (const float*)d_in[10];
    const float* ln2_b  = (const float*)d_in[11];
    const float* w1     = (const float*)d_in[12];
    const float* b1     = (const float*)d_in[13];
    const float* w2     = (const float*)d_in[14];
    const float* b2     = (const float*)d_in[15];
    const float* lnf_g  = (const float*)d_in[16];
    const float* lnf_b  = (const float*)d_in[17];
    const float* lm_w   = (const float*)d_in[18];
    const float* lm_b   = (const float*)d_in[19];
    float* out = (float*)d_out;

    float *X, *Hb, *Q, *K, *V, *Att, *FF, *W;
    cudaGetSymbolAddress((void**)&X,   g_X);
    cudaGetSymbolAddress((void**)&Hb,  g_Hb);
    cudaGetSymbolAddress((void**)&Q,   g_Q);
    cudaGetSymbolAddress((void**)&K,   g_K);
    cudaGetSymbolAddress((void**)&V,   g_V);
    cudaGetSymbolAddress((void**)&Att, g_Att);
    cudaGetSymbolAddress((void**)&FF,  g_FF);
    cudaGetSymbolAddress((void**)&W,   g_W);

    embed_k<<<BT, 256>>>(idx, tok, pos, X);

    dim3 gC(Cn/128, BT/128);      // N=256
    dim3 gF(DFFn/128, BT/128);    // N=1024
    dim3 gV((Vn + 127)/128, BT/128);

    for (int l = 0; l < Ln; l++) {
        ln_k<<<BT, 256>>>(X, Hb, ln1_g + l*Cn, ln1_b + l*Cn);

        tcgemm_k<0><<<gC, 256>>>(BT, Cn, Cn, Hb, Cn, wq + (size_t)l*Cn*Cn, Cn,
                                 nullptr, nullptr, Q, Cn);
        tcgemm_k<0><<<gC, 256>>>(BT, Cn, Cn, Hb, Cn, wk + (size_t)l*Cn*Cn, Cn,
                                 nullptr, nullptr, K, Cn);
        tcgemm_k<0><<<gC, 256>>>(BT, Cn, Cn, Hb, Cn, wv + (size_t)l*Cn*Cn, Cn,
                                 nullptr, nullptr, V, Cn);

        scores_k<<<Bv*Hn, 256>>>(Q, K, W);
        softmax_k<<<Bv*Hn*Tn/8, 256>>>(W);
        av_k<<<Bv*Hn, 256>>>(W, V, Att);

        // x = x + att @ proj_w + proj_b
        tcgemm_k<3><<<gC, 256>>>(BT, Cn, Cn, Att, Cn, proj_w + (size_t)l*Cn*Cn, Cn,
                                 proj_b + l*Cn, X, X, Cn);

        ln_k<<<BT, 256>>>(X, Hb, ln2_g + l*Cn, ln2_b + l*Cn);

        // ff = relu(h2 @ w1 + b1)
        tcgemm_k<5><<<gF, 256>>>(BT, DFFn, Cn, Hb, Cn, w1 + (size_t)l*Cn*DFFn, DFFn,
                                 b1 + l*DFFn, nullptr, FF, DFFn);
        // x = x + ff @ w2 + b2
        tcgemm_k<3><<<gC, 256>>>(BT, Cn, DFFn, FF, DFFn, w2 + (size_t)l*DFFn*Cn, Cn,
                                 b2 + l*Cn, X, X, Cn);
    }

    ln_k<<<BT, 256>>>(X, Hb, lnf_g, lnf_b);
    tcgemm_k<1><<<gV, 256>>>(BT, Vn, Cn, Hb, Cn, lm_w, Vn,
                             lm_b, nullptr, out, Vn);
}

// round 5
// speedup vs baseline: 1.7759x; 1.1165x over previous
#include <cuda_runtime.h>
#include <math.h>

// Problem constants
#define Bv   128
#define Tn   128
#define Cn   256
#define Hn   4
#define Ln   6
#define Vn   10000
#define HSn  64
#define DFFn 1024
#define BT   (Bv*Tn)   // 16384 rows

// ---------------- scratch (device globals; no allocation allowed) ----------
__device__ float g_X  [BT*Cn];     // residual stream
__device__ float g_Hb [BT*Cn];     // layernorm output (tf32-rounded)
__device__ float g_Q  [BT*Cn];
__device__ float g_K  [BT*Cn];
__device__ float g_V  [BT*Cn];
__device__ float g_Att[BT*Cn];     // attention out (tf32-rounded)
__device__ float g_FF [BT*DFFn];   // relu MLP hidden (tf32-rounded)
__device__ float g_W  [Bv*Hn*Tn*Tn];   // attention probs

// pre-rounded (tf32 grid) weights
#define RW_WQ 0
#define RW_WK 393216
#define RW_WV 786432
#define RW_PJ 1179648
#define RW_W1 1572864
#define RW_W2 3145728
#define RW_LM 4718592
#define RW_TOT 7278592
__device__ float g_rW [RW_TOT];

// ---------------- helpers ---------------------------------------------------
__device__ __forceinline__ unsigned f2tf32(float x) {
    unsigned r;
    asm("cvt.rna.tf32.f32 %0, %1;" : "=r"(r) : "f"(x));
    return r;
}
__device__ __forceinline__ float roundtf(float x) {
    return __uint_as_float(f2tf32(x));
}

__device__ __forceinline__ void mma_tf32(float* c, const unsigned* a, const unsigned* b) {
    asm volatile(
        "mma.sync.aligned.m16n8k8.row.col.f32.tf32.tf32.f32 "
        "{%0,%1,%2,%3}, {%4,%5,%6,%7}, {%8,%9}, {%0,%1,%2,%3};"
        : "+f"(c[0]), "+f"(c[1]), "+f"(c[2]), "+f"(c[3])
        : "r"(a[0]), "r"(a[1]), "r"(a[2]), "r"(a[3]), "r"(b[0]), "r"(b[1]));
}

__device__ __forceinline__ void cp16(unsigned dst_smem, const void* src) {
    asm volatile("cp.async.cg.shared.global [%0], [%1], 16;"
                 :: "r"(dst_smem), "l"(src));
}
__device__ __forceinline__ void cp16z(unsigned dst_smem, const void* src, int sz) {
    asm volatile("cp.async.cg.shared.global [%0], [%1], 16, %2;"
                 :: "r"(dst_smem), "l"(src), "r"(sz));
}
__device__ __forceinline__ void cp_commit() {
    asm volatile("cp.async.commit_group;" ::);
}
__device__ __forceinline__ void cp_wait0() {
    asm volatile("cp.async.wait_group 0;" ::);
}

// ---------------- weight pre-rounding --------------------------------------
__global__ void roundw_k(const float* __restrict__ in, float* __restrict__ out, int n)
{
    for (int i = blockIdx.x*256 + threadIdx.x; i < n; i += gridDim.x*256)
        out[i] = roundtf(in[i]);
}

// ---------------- embedding ------------------------------------------------
__global__ void embed_k(const int* __restrict__ idx,
                        const float* __restrict__ tok,
                        const float* __restrict__ pos,
                        float* __restrict__ X)
{
    int bt = blockIdx.x;
    int c  = threadIdx.x;
    int t  = bt % Tn;
    int id = idx[bt];
    X[bt*Cn + c] = tok[id*Cn + c] + pos[t*Cn + c];
}

// ---------------- layernorm (output rounded to tf32 grid) ------------------
__global__ void ln_k(const float* __restrict__ in, float* __restrict__ out,
                     const float* __restrict__ g, const float* __restrict__ b)
{
    int row = blockIdx.x;
    int c   = threadIdx.x;
    __shared__ float sbuf[256];
    float v = in[row*Cn + c];
    sbuf[c] = v; __syncthreads();
    #pragma unroll
    for (int s = 128; s > 0; s >>= 1) { if (c < s) sbuf[c] += sbuf[c+s]; __syncthreads(); }
    float mean = sbuf[0] * (1.0f/Cn);
    __syncthreads();
    float d = v - mean;
    sbuf[c] = d*d; __syncthreads();
    #pragma unroll
    for (int s = 128; s > 0; s >>= 1) { if (c < s) sbuf[c] += sbuf[c+s]; __syncthreads(); }
    float var = sbuf[0] * (1.0f/Cn);
    float r = rsqrtf(var + 1e-5f);
    out[row*Cn + c] = roundtf(d * r * g[c] + b[c]);
}

// ---------------- TF32 tensor-core GEMM (cp.async double-buffered) ----------
// Operands must be pre-rounded to tf32 grid. BM=BN=128, BK=16, 8 warps.
// EPI bit0 = +bias[n], bit1 = +res, bit2 = relu, bit3 = round output to tf32
template<int EPI>
__global__ void __launch_bounds__(256, 2)
tcgemm_k(int M, int N, int K,
         const float* __restrict__ A, int lda,
         const float* __restrict__ B, int ldb,
         const float* __restrict__ bias,
         const float* __restrict__ res,
         float* __restrict__ C, int ldc)
{
    __shared__ unsigned As[2][128][20];   // [stage][m][k], pad 20 -> conflict-free
    __shared__ unsigned Bs[2][16][136];   // [stage][k][n], pad 136 -> conflict-free

    int tid  = threadIdx.x;
    int wid  = tid >> 5, lane = tid & 31;
    int grp  = lane >> 2, tg = lane & 3;
    int wm   = (wid & 3) * 32;
    int wn   = (wid >> 2) * 64;
    int bm   = blockIdx.y * 128, bn = blockIdx.x * 128;

    float acc[2][8][4];
    #pragma unroll
    for (int mt = 0; mt < 2; mt++)
        #pragma unroll
        for (int nt = 0; nt < 8; nt++)
            #pragma unroll
            for (int r = 0; r < 4; r++) acc[mt][nt][r] = 0.f;

    // cp.async indices: A tile 128x16 = 512 16B-chunks; B tile 16x128 = 512 chunks
    int aRow = tid >> 1;                 // chunk it=0: rows 0..127 via c=tid
    // we use c = tid + it*256; row = c>>2, kc = (c&3)*4
    // B: c = tid + it*256; krow = c>>5, nc = (c&31)*4

    int niter = K >> 4;

    // ---- issue stage 0 ----
    {
        #pragma unroll
        for (int it = 0; it < 2; it++) {
            int c = tid + it*256;
            int row = c >> 2, kc = (c & 3) * 4;
            unsigned d = (unsigned)__cvta_generic_to_shared(&As[0][row][kc]);
            cp16(d, A + (size_t)(bm + row)*lda + kc);
        }
        #pragma unroll
        for (int it = 0; it < 2; it++) {
            int c = tid + it*256;
            int kr = c >> 5, nc = (c & 31) * 4;
            unsigned d = (unsigned)__cvta_generic_to_shared(&Bs[0][kr][nc]);
            int col = bn + nc;
            cp16z(d, B + (size_t)kr*ldb + (col < N ? col : 0), col < N ? 16 : 0);
        }
        cp_commit();
    }

    for (int i = 0; i < niter; i++) {
        int s = i & 1;
        cp_wait0();
        __syncthreads();   // stage i visible everywhere; stage s^1 fully consumed

        if (i + 1 < niter) {
            int k0 = (i + 1) << 4;
            #pragma unroll
            for (int it = 0; it < 2; it++) {
                int c = tid + it*256;
                int row = c >> 2, kc = (c & 3) * 4;
                unsigned d = (unsigned)__cvta_generic_to_shared(&As[s^1][row][kc]);
                cp16(d, A + (size_t)(bm + row)*lda + k0 + kc);
            }
            #pragma unroll
            for (int it = 0; it < 2; it++) {
                int c = tid + it*256;
                int kr = c >> 5, nc = (c & 31) * 4;
                unsigned d = (unsigned)__cvta_generic_to_shared(&Bs[s^1][kr][nc]);
                int col = bn + nc;
                cp16z(d, B + (size_t)(k0 + kr)*ldb + (col < N ? col : 0),
                      col < N ? 16 : 0);
            }
            cp_commit();
        }

        #pragma unroll
        for (int ks = 0; ks < 2; ks++) {
            int k = ks*8;
            unsigned bfr[8][2];
            #pragma unroll
            for (int nt = 0; nt < 8; nt++) {
                bfr[nt][0] = Bs[s][k+tg  ][wn + nt*8 + grp];
                bfr[nt][1] = Bs[s][k+tg+4][wn + nt*8 + grp];
            }
            #pragma unroll
            for (int mt = 0; mt < 2; mt++) {
                unsigned afr[4];
                afr[0] = As[s][wm + mt*16 + grp    ][k + tg    ];
                afr[1] = As[s][wm + mt*16 + grp + 8][k + tg    ];
                afr[2] = As[s][wm + mt*16 + grp    ][k + tg + 4];
                afr[3] = As[s][wm + mt*16 + grp + 8][k + tg + 4];
                #pragma unroll
                for (int nt = 0; nt < 8; nt++)
                    mma_tf32(acc[mt][nt], afr, bfr[nt]);
            }
        }
    }

    // epilogue
    #pragma unroll
    for (int mt = 0; mt < 2; mt++) {
        int r0 = bm + wm + mt*16 + grp;
        #pragma unroll
        for (int nt = 0; nt < 8; nt++) {
            int c0 = bn + wn + nt*8 + 2*tg;
            #pragma unroll
            for (int half = 0; half < 2; half++) {
                int r = r0 + half*8;
                float v0 = acc[mt][nt][half*2+0];
                float v1 = acc[mt][nt][half*2+1];
                if (c0 < N) {
                    if (EPI & 1) v0 += bias[c0];
                    if (EPI & 2) v0 += res[(size_t)r*ldc + c0];
                    if (EPI & 4) v0 = fmaxf(v0, 0.f);
                    if (EPI & 8) v0 = roundtf(v0);
                    C[(size_t)r*ldc + c0] = v0;
                }
                if (c0 + 1 < N) {
                    if (EPI & 1) v1 += bias[c0+1];
                    if (EPI & 2) v1 += res[(size_t)r*ldc + c0+1];
                    if (EPI & 4) v1 = fmaxf(v1, 0.f);
                    if (EPI & 8) v1 = roundtf(v1);
                    C[(size_t)r*ldc + c0+1] = v1;
                }
            }
        }
    }
}

// ---------------- attention scores: S[q,k] = scale * <Q_q, K_k> ------------
__global__ void __launch_bounds__(256, 2)
scores_k(const float* __restrict__ Q, const float* __restrict__ K,
         float* __restrict__ W)
{
    int bh = blockIdx.x;
    int b = bh >> 2, h = bh & 3;
    const float* Qp = Q + (size_t)b*Tn*Cn + h*HSn;
    const float* Kp = K + (size_t)b*Tn*Cn + h*HSn;
    float* Wp = W + (size_t)bh*Tn*Tn;

    __shared__ float Qs[16][128];
    __shared__ float Ks[16][128];
    int tid = threadIdx.x;
    int tx = tid & 15, ty = tid >> 4;

    float acc[8][8];
    #pragma unroll
    for (int i = 0; i < 8; i++)
        #pragma unroll
        for (int j = 0; j < 8; j++) acc[i][j] = 0.f;

    for (int d0 = 0; d0 < HSn; d0 += 16) {
        #pragma unroll
        for (int it = 0; it < 2; it++) {
            int v  = tid + it*256;
            int q  = v >> 2;
            int f4 = (v & 3) * 4;
            float4 qa = *(const float4*)(Qp + (size_t)q*Cn + d0 + f4);
            Qs[f4+0][q] = qa.x; Qs[f4+1][q] = qa.y;
            Qs[f4+2][q] = qa.z; Qs[f4+3][q] = qa.w;
            float4 ka = *(const float4*)(Kp + (size_t)q*Cn + d0 + f4);
            Ks[f4+0][q] = ka.x; Ks[f4+1][q] = ka.y;
            Ks[f4+2][q] = ka.z; Ks[f4+3][q] = ka.w;
        }
        __syncthreads();
        #pragma unroll
        for (int kk = 0; kk < 16; kk++) {
            float4 a0 = *(float4*)&Qs[kk][ty*4];
            float4 a1 = *(float4*)&Qs[kk][ty*4 + 64];
            float4 b0 = *(float4*)&Ks[kk][tx*4];
            float4 b1 = *(float4*)&Ks[kk][tx*4 + 64];
            float af[8] = {a0.x,a0.y,a0.z,a0.w,a1.x,a1.y,a1.z,a1.w};
            float bf[8] = {b0.x,b0.y,b0.z,b0.w,b1.x,b1.y,b1.z,b1.w};
            #pragma unroll
            for (int i = 0; i < 8; i++)
                #pragma unroll
                for (int j = 0; j < 8; j++)
                    acc[i][j] += af[i]*bf[j];
        }
        __syncthreads();
    }

    const float scale = 0.0625f;   // 1/sqrt(256)
    #pragma unroll
    for (int i = 0; i < 8; i++) {
        int q = (i < 4) ? (ty*4 + i) : (64 + ty*4 + i - 4);
        #pragma unroll
        for (int j = 0; j < 8; j++) {
            int k = (j < 4) ? (tx*4 + j) : (64 + tx*4 + j - 4);
            Wp[q*Tn + k] = acc[i][j] * scale;
        }
    }
}

// ---------------- causal softmax over rows of W (length 128) ---------------
__global__ void softmax_k(float* __restrict__ W)
{
    int row  = blockIdx.x * 8 + (threadIdx.x >> 5);
    int lane = threadIdx.x & 31;
    int q = row % Tn;
    float* p = W + (size_t)row*Tn;

    float4 v = *(float4*)(p + lane*4);
    float vals[4] = {v.x, v.y, v.z, v.w};
    float mx = -1e30f;
    #pragma unroll
    for (int i = 0; i < 4; i++) {
        int k = lane*4 + i;
        if (k > q) vals[i] = -1e30f;
        mx = fmaxf(mx, vals[i]);
    }
    #pragma unroll
    for (int s = 16; s > 0; s >>= 1)
        mx = fmaxf(mx, __shfl_xor_sync(0xFFFFFFFF, mx, s));
    float sum = 0.f;
    #pragma unroll
    for (int i = 0; i < 4; i++) {
        int k = lane*4 + i;
        vals[i] = (k > q) ? 0.f : __expf(vals[i] - mx);
        sum += vals[i];
    }
    #pragma unroll
    for (int s = 16; s > 0; s >>= 1)
        sum += __shfl_xor_sync(0xFFFFFFFF, sum, s);
    float inv = 1.f / sum;
    *(float4*)(p + lane*4) = make_float4(vals[0]*inv, vals[1]*inv, vals[2]*inv, vals[3]*inv);
}

// ---------------- AV: O[q,d] = sum_k P[q,k] V[k,d] (output tf32-rounded) ----
__global__ void __launch_bounds__(256, 2)
av_k(const float* __restrict__ W, const float* __restrict__ V,
     float* __restrict__ Att)
{
    int bh = blockIdx.x;
    int b = bh >> 2, h = bh & 3;
    const float* Wp = W + (size_t)bh*Tn*Tn;
    const float* Vp = V + (size_t)b*Tn*Cn + h*HSn;
    float* Op = Att + (size_t)b*Tn*Cn + h*HSn;

    __shared__ float Ps[16][128];
    __shared__ float Vs[16][64];
    int tid = threadIdx.x;
    int tx = tid & 15, ty = tid >> 4;

    float acc[8][4];
    #pragma unroll
    for (int i = 0; i < 8; i++)
        #pragma unroll
        for (int j = 0; j < 4; j++) acc[i][j] = 0.f;

    for (int k0 = 0; k0 < Tn; k0 += 16) {
        #pragma unroll
        for (int it = 0; it < 2; it++) {
            int v  = tid + it*256;
            int q  = v >> 2;
            int f4 = (v & 3) * 4;
            float4 pa = *(const float4*)(Wp + (size_t)q*Tn + k0 + f4);
            Ps[f4+0][q] = pa.x; Ps[f4+1][q] = pa.y;
            Ps[f4+2][q] = pa.z; Ps[f4+3][q] = pa.w;
        }
        {
            int kk = tid >> 4;
            int d4 = (tid & 15) * 4;
            float4 va = *(const float4*)(Vp + (size_t)(k0 + kk)*Cn + d4);
            *(float4*)&Vs[kk][d4] = va;
        }
        __syncthreads();
        #pragma unroll
        for (int kk = 0; kk < 16; kk++) {
            float4 a0 = *(float4*)&Ps[kk][ty*4];
            float4 a1 = *(float4*)&Ps[kk][ty*4 + 64];
            float4 b0 = *(float4*)&Vs[kk][tx*4];
            float af[8] = {a0.x,a0.y,a0.z,a0.w,a1.x,a1.y,a1.z,a1.w};
            float bf[4] = {b0.x,b0.y,b0.z,b0.w};
            #pragma unroll
            for (int i = 0; i < 8; i++)
                #pragma unroll
                for (int j = 0; j < 4; j++)
                    acc[i][j] += af[i]*bf[j];
        }
        __syncthreads();
    }

    #pragma unroll
    for (int i = 0; i < 8; i++) {
        int q = (i < 4) ? (ty*4 + i) : (64 + ty*4 + i - 4);
        #pragma unroll
        for (int j = 0; j < 4; j++) {
            int d = tx*4 + j;
            Op[(size_t)q*Cn + d] = roundtf(acc[i][j]);
        }
    }
}

// ---------------- host launcher --------------------------------------------
extern "C" void kernel_launch(void* const* d_in, const int* in_sizes, int n_in,
                              void* d_out, int out_size)
{
    const int*   idx    = (const int*)  d_in[0];
    const float* tok    = (const float*)d_in[1];
    const float* pos    = (const float*)d_in[2];
    const float* ln1_g  = (const float*)d_in[3];
    const float* ln1_b  = (const float*)d_in[4];
    const float* wq     = (const float*)d_in[5];
    const float* wk     = (const float*)d_in[6];
    const float* wv     = (const float*)d_in[7];
    const float* proj_w = (const float*)d_in[8];
    const float* proj_b = (const float*)d_in[9];
    const float* ln2_g  = (const float*)d_in[10];
    const float* ln2_b  = (const float*)d_in[11];
    const float* w1     = (const float*)d_in[12];
    const float* b1     = (const float*)d_in[13];
    const float* w2     = (const float*)d_in[14];
    const float* b2     = (const float*)d_in[15];
    const float* lnf_g  = (const float*)d_in[16];
    const float* lnf_b  = (const float*)d_in[17];
    const float* lm_w   = (const float*)d_in[18];
    const float* lm_b   = (const float*)d_in[19];
    float* out = (float*)d_out;

    float *X, *Hb, *Q, *K, *V, *Att, *FF, *W, *rW;
    cudaGetSymbolAddress((void**)&X,   g_X);
    cudaGetSymbolAddress((void**)&Hb,  g_Hb);
    cudaGetSymbolAddress((void**)&Q,   g_Q);
    cudaGetSymbolAddress((void**)&K,   g_K);
    cudaGetSymbolAddress((void**)&V,   g_V);
    cudaGetSymbolAddress((void**)&Att, g_Att);
    cudaGetSymbolAddress((void**)&FF,  g_FF);
    cudaGetSymbolAddress((void**)&W,   g_W);
    cudaGetSymbolAddress((void**)&rW,  g_rW);

    // pre-round all weights to tf32 grid
    roundw_k<<<512, 256>>>(wq,     rW + RW_WQ, Ln*Cn*Cn);
    roundw_k<<<512, 256>>>(wk,     rW + RW_WK, Ln*Cn*Cn);
    roundw_k<<<512, 256>>>(wv,     rW + RW_WV, Ln*Cn*Cn);
    roundw_k<<<512, 256>>>(proj_w, rW + RW_PJ, Ln*Cn*Cn);
    roundw_k<<<512, 256>>>(w1,     rW + RW_W1, Ln*Cn*DFFn);
    roundw_k<<<512, 256>>>(w2,     rW + RW_W2, Ln*DFFn*Cn);
    roundw_k<<<512, 256>>>(lm_w,   rW + RW_LM, Cn*Vn);

    embed_k<<<BT, 256>>>(idx, tok, pos, X);

    dim3 gC(Cn/128, BT/128);      // N=256
    dim3 gF(DFFn/128, BT/128);    // N=1024
    dim3 gV((Vn + 127)/128, BT/128);

    for (int l = 0; l < Ln; l++) {
        ln_k<<<BT, 256>>>(X, Hb, ln1_g + l*Cn, ln1_b + l*Cn);

        tcgemm_k<0><<<gC, 256>>>(BT, Cn, Cn, Hb, Cn, rW + RW_WQ + (size_t)l*Cn*Cn, Cn,
                                 nullptr, nullptr, Q, Cn);
        tcgemm_k<0><<<gC, 256>>>(BT, Cn, Cn, Hb, Cn, rW + RW_WK + (size_t)l*Cn*Cn, Cn,
                                 nullptr, nullptr, K, Cn);
        tcgemm_k<0><<<gC, 256>>>(BT, Cn, Cn, Hb, Cn, rW + RW_WV + (size_t)l*Cn*Cn, Cn,
                                 nullptr, nullptr, V, Cn);

        scores_k<<<Bv*Hn, 256>>>(Q, K, W);
        softmax_k<<<Bv*Hn*Tn/8, 256>>>(W);
        av_k<<<Bv*Hn, 256>>>(W, V, Att);

        // x = x + att @ proj_w + proj_b
        tcgemm_k<3><<<gC, 256>>>(BT, Cn, Cn, Att, Cn, rW + RW_PJ + (size_t)l*Cn*Cn, Cn,
                                 proj_b + l*Cn, X, X, Cn);

        ln_k<<<BT, 256>>>(X, Hb, ln2_g + l*Cn, ln2_b + l*Cn);

        // ff = relu(h2 @ w1 + b1)  (rounded to tf32 grid)
        tcgemm_k<13><<<gF, 256>>>(BT, DFFn, Cn, Hb, Cn, rW + RW_W1 + (size_t)l*Cn*DFFn, DFFn,
                                  b1 + l*DFFn, nullptr, FF, DFFn);
        // x = x + ff @ w2 + b2
        tcgemm_k<3><<<gC, 256>>>(BT, Cn, DFFn, FF, DFFn, rW + RW_W2 + (size_t)l*DFFn*Cn, Cn,
                                 b2 + l*Cn, X, X, Cn);
    }

    ln_k<<<BT, 256>>>(X, Hb, lnf_g, lnf_b);
    tcgemm_k<1><<<gV, 256>>>(BT, Vn, Cn, Hb, Cn, rW + RW_LM, Vn,
                             lm_b, nullptr, out, Vn);
}

// round 6
// speedup vs baseline: 1.8125x; 1.0206x over previous
#include <cuda_runtime.h>
#include <math.h>

// Problem constants
#define Bv   128
#define Tn   128
#define Cn   256
#define Hn   4
#define Ln   6
#define Vn   10000
#define HSn  64
#define DFFn 1024
#define BT   (Bv*Tn)   // 16384 rows

// ---------------- scratch (device globals; no allocation allowed) ----------
__device__ float g_X  [BT*Cn];      // residual stream
__device__ float g_Hb [BT*Cn];      // layernorm output (tf32-rounded)
__device__ float g_QKV[BT*768];     // fused QKV output [row][768]
__device__ float g_Att[BT*Cn];      // attention out (tf32-rounded)
__device__ float g_FF [BT*DFFn];    // relu MLP hidden (tf32-rounded)
__device__ float g_W  [Bv*Hn*Tn*Tn];// attention probs

// pre-rounded (tf32 grid) weights
#define RW_QKV 0                        // packed [L][C][768]
#define RW_PJ  1179648
#define RW_W1  1572864
#define RW_W2  3145728
#define RW_LM  4718592
#define RW_TOT 7278592
__device__ float g_rW [RW_TOT];

// ---------------- helpers ---------------------------------------------------
__device__ __forceinline__ unsigned f2tf32(float x) {
    unsigned r;
    asm("cvt.rna.tf32.f32 %0, %1;" : "=r"(r) : "f"(x));
    return r;
}
__device__ __forceinline__ float roundtf(float x) {
    return __uint_as_float(f2tf32(x));
}

__device__ __forceinline__ void mma_tf32(float* c, const unsigned* a, const unsigned* b) {
    asm volatile(
        "mma.sync.aligned.m16n8k8.row.col.f32.tf32.tf32.f32 "
        "{%0,%1,%2,%3}, {%4,%5,%6,%7}, {%8,%9}, {%0,%1,%2,%3};"
        : "+f"(c[0]), "+f"(c[1]), "+f"(c[2]), "+f"(c[3])
        : "r"(a[0]), "r"(a[1]), "r"(a[2]), "r"(a[3]), "r"(b[0]), "r"(b[1]));
}

__device__ __forceinline__ void cp16(unsigned dst_smem, const void* src) {
    asm volatile("cp.async.cg.shared.global [%0], [%1], 16;"
                 :: "r"(dst_smem), "l"(src));
}
__device__ __forceinline__ void cp16z(unsigned dst_smem, const void* src, int sz) {
    asm volatile("cp.async.cg.shared.global [%0], [%1], 16, %2;"
                 :: "r"(dst_smem), "l"(src), "r"(sz));
}
__device__ __forceinline__ void cp_commit() {
    asm volatile("cp.async.commit_group;" ::);
}
__device__ __forceinline__ void cp_wait0() {
    asm volatile("cp.async.wait_group 0;" ::);
}

// ---------------- weight pre-rounding --------------------------------------
__global__ void roundw_k(const float* __restrict__ in, float* __restrict__ out, int n)
{
    for (int i = blockIdx.x*256 + threadIdx.x; i < n; i += gridDim.x*256)
        out[i] = roundtf(in[i]);
}

// pack wq|wk|wv -> interleaved [L][C][768], tf32-rounded
__global__ void packqkv_k(const float* __restrict__ wq,
                          const float* __restrict__ wk,
                          const float* __restrict__ wv,
                          float* __restrict__ out)
{
    int n = Ln*Cn*768;
    for (int i = blockIdx.x*256 + threadIdx.x; i < n; i += gridDim.x*256) {
        int l = i / (Cn*768);
        int r = i % (Cn*768);
        int c = r / 768;
        int j = r % 768;
        float v;
        int base = l*Cn*Cn + c*Cn;   // Cn == 256 == H*HS
        if (j < 256)      v = wq[base + j];
        else if (j < 512) v = wk[base + j - 256];
        else              v = wv[base + j - 512];
        out[i] = roundtf(v);
    }
}

// ---------------- embedding ------------------------------------------------
__global__ void embed_k(const int* __restrict__ idx,
                        const float* __restrict__ tok,
                        const float* __restrict__ pos,
                        float* __restrict__ X)
{
    int bt = blockIdx.x;
    int c  = threadIdx.x;
    int t  = bt % Tn;
    int id = idx[bt];
    X[bt*Cn + c] = tok[id*Cn + c] + pos[t*Cn + c];
}

// ---------------- layernorm (output rounded to tf32 grid) ------------------
__global__ void ln_k(const float* __restrict__ in, float* __restrict__ out,
                     const float* __restrict__ g, const float* __restrict__ b)
{
    int row = blockIdx.x;
    int c   = threadIdx.x;
    __shared__ float sbuf[256];
    float v = in[row*Cn + c];
    sbuf[c] = v; __syncthreads();
    #pragma unroll
    for (int s = 128; s > 0; s >>= 1) { if (c < s) sbuf[c] += sbuf[c+s]; __syncthreads(); }
    float mean = sbuf[0] * (1.0f/Cn);
    __syncthreads();
    float d = v - mean;
    sbuf[c] = d*d; __syncthreads();
    #pragma unroll
    for (int s = 128; s > 0; s >>= 1) { if (c < s) sbuf[c] += sbuf[c+s]; __syncthreads(); }
    float var = sbuf[0] * (1.0f/Cn);
    float r = rsqrtf(var + 1e-5f);
    out[row*Cn + c] = roundtf(d * r * g[c] + b[c]);
}

// ---------------- TF32 tensor-core GEMM (cp.async double-buffered) ----------
// Operands must be pre-rounded to tf32 grid. BM=BN=128, BK=16, 8 warps.
// EPI bit0 = +bias[n], bit1 = +res, bit2 = relu, bit3 = round output to tf32
template<int EPI>
__global__ void __launch_bounds__(256, 2)
tcgemm_k(int M, int N, int K,
         const float* __restrict__ A, int lda,
         const float* __restrict__ B, int ldb,
         const float* __restrict__ bias,
         const float* __restrict__ res,
         float* __restrict__ C, int ldc)
{
    __shared__ unsigned As[2][128][20];   // [stage][m][k]
    __shared__ unsigned Bs[2][16][136];   // [stage][k][n]

    int tid  = threadIdx.x;
    int wid  = tid >> 5, lane = tid & 31;
    int grp  = lane >> 2, tg = lane & 3;
    int wm   = (wid & 3) * 32;
    int wn   = (wid >> 2) * 64;
    int bm   = blockIdx.y * 128, bn = blockIdx.x * 128;

    float acc[2][8][4];
    #pragma unroll
    for (int mt = 0; mt < 2; mt++)
        #pragma unroll
        for (int nt = 0; nt < 8; nt++)
            #pragma unroll
            for (int r = 0; r < 4; r++) acc[mt][nt][r] = 0.f;

    int niter = K >> 4;

    // ---- issue stage 0 ----
    {
        #pragma unroll
        for (int it = 0; it < 2; it++) {
            int c = tid + it*256;
            int row = c >> 2, kc = (c & 3) * 4;
            unsigned d = (unsigned)__cvta_generic_to_shared(&As[0][row][kc]);
            cp16(d, A + (size_t)(bm + row)*lda + kc);
        }
        #pragma unroll
        for (int it = 0; it < 2; it++) {
            int c = tid + it*256;
            int kr = c >> 5, nc = (c & 31) * 4;
            unsigned d = (unsigned)__cvta_generic_to_shared(&Bs[0][kr][nc]);
            int col = bn + nc;
            cp16z(d, B + (size_t)kr*ldb + (col < N ? col : 0), col < N ? 16 : 0);
        }
        cp_commit();
    }

    for (int i = 0; i < niter; i++) {
        int s = i & 1;
        cp_wait0();
        __syncthreads();

        if (i + 1 < niter) {
            int k0 = (i + 1) << 4;
            #pragma unroll
            for (int it = 0; it < 2; it++) {
                int c = tid + it*256;
                int row = c >> 2, kc = (c & 3) * 4;
                unsigned d = (unsigned)__cvta_generic_to_shared(&As[s^1][row][kc]);
                cp16(d, A + (size_t)(bm + row)*lda + k0 + kc);
            }
            #pragma unroll
            for (int it = 0; it < 2; it++) {
                int c = tid + it*256;
                int kr = c >> 5, nc = (c & 31) * 4;
                unsigned d = (unsigned)__cvta_generic_to_shared(&Bs[s^1][kr][nc]);
                int col = bn + nc;
                cp16z(d, B + (size_t)(k0 + kr)*ldb + (col < N ? col : 0),
                      col < N ? 16 : 0);
            }
            cp_commit();
        }

        #pragma unroll
        for (int ks = 0; ks < 2; ks++) {
            int k = ks*8;
            unsigned bfr[8][2];
            #pragma unroll
            for (int nt = 0; nt < 8; nt++) {
                bfr[nt][0] = Bs[s][k+tg  ][wn + nt*8 + grp];
                bfr[nt][1] = Bs[s][k+tg+4][wn + nt*8 + grp];
            }
            #pragma unroll
            for (int mt = 0; mt < 2; mt++) {
                unsigned afr[4];
                afr[0] = As[s][wm + mt*16 + grp    ][k + tg    ];
                afr[1] = As[s][wm + mt*16 + grp + 8][k + tg    ];
                afr[2] = As[s][wm + mt*16 + grp    ][k + tg + 4];
                afr[3] = As[s][wm + mt*16 + grp + 8][k + tg + 4];
                #pragma unroll
                for (int nt = 0; nt < 8; nt++)
                    mma_tf32(acc[mt][nt], afr, bfr[nt]);
            }
        }
    }

    // epilogue
    #pragma unroll
    for (int mt = 0; mt < 2; mt++) {
        int r0 = bm + wm + mt*16 + grp;
        #pragma unroll
        for (int nt = 0; nt < 8; nt++) {
            int c0 = bn + wn + nt*8 + 2*tg;
            #pragma unroll
            for (int half = 0; half < 2; half++) {
                int r = r0 + half*8;
                float v0 = acc[mt][nt][half*2+0];
                float v1 = acc[mt][nt][half*2+1];
                if (c0 < N) {
                    if (EPI & 1) v0 += bias[c0];
                    if (EPI & 2) v0 += res[(size_t)r*ldc + c0];
                    if (EPI & 4) v0 = fmaxf(v0, 0.f);
                    if (EPI & 8) v0 = roundtf(v0);
                    C[(size_t)r*ldc + c0] = v0;
                }
                if (c0 + 1 < N) {
                    if (EPI & 1) v1 += bias[c0+1];
                    if (EPI & 2) v1 += res[(size_t)r*ldc + c0+1];
                    if (EPI & 4) v1 = fmaxf(v1, 0.f);
                    if (EPI & 8) v1 = roundtf(v1);
                    C[(size_t)r*ldc + c0+1] = v1;
                }
            }
        }
    }
}

// ---------------- attention scores + causal softmax (fused) -----------------
// one block per (b,h). Q/K read from g_QKV (stride 768), probs written to W.
// Thread (tx,ty): rows q(i) from ty, cols k(j) from tx. The 16 threads with
// equal ty form a contiguous half-warp -> row reductions via shfl_xor(1,2,4,8).
__global__ void __launch_bounds__(256, 2)
scores_k(const float* __restrict__ QKV, float* __restrict__ W)
{
    int bh = blockIdx.x;
    int b = bh >> 2, h = bh & 3;
    const float* Qp = QKV + (size_t)b*Tn*768 + h*HSn;
    const float* Kp = QKV + (size_t)b*Tn*768 + 256 + h*HSn;
    float* Wp = W + (size_t)bh*Tn*Tn;

    __shared__ float Qs[16][128];
    __shared__ float Ks[16][128];
    int tid = threadIdx.x;
    int tx = tid & 15, ty = tid >> 4;

    float acc[8][8];
    #pragma unroll
    for (int i = 0; i < 8; i++)
        #pragma unroll
        for (int j = 0; j < 8; j++) acc[i][j] = 0.f;

    for (int d0 = 0; d0 < HSn; d0 += 16) {
        #pragma unroll
        for (int it = 0; it < 2; it++) {
            int v  = tid + it*256;
            int q  = v >> 2;
            int f4 = (v & 3) * 4;
            float4 qa = *(const float4*)(Qp + (size_t)q*768 + d0 + f4);
            Qs[f4+0][q] = qa.x; Qs[f4+1][q] = qa.y;
            Qs[f4+2][q] = qa.z; Qs[f4+3][q] = qa.w;
            float4 ka = *(const float4*)(Kp + (size_t)q*768 + d0 + f4);
            Ks[f4+0][q] = ka.x; Ks[f4+1][q] = ka.y;
            Ks[f4+2][q] = ka.z; Ks[f4+3][q] = ka.w;
        }
        __syncthreads();
        #pragma unroll
        for (int kk = 0; kk < 16; kk++) {
            float4 a0 = *(float4*)&Qs[kk][ty*4];
            float4 a1 = *(float4*)&Qs[kk][ty*4 + 64];
            float4 b0 = *(float4*)&Ks[kk][tx*4];
            float4 b1 = *(float4*)&Ks[kk][tx*4 + 64];
            float af[8] = {a0.x,a0.y,a0.z,a0.w,a1.x,a1.y,a1.z,a1.w};
            float bf[8] = {b0.x,b0.y,b0.z,b0.w,b1.x,b1.y,b1.z,b1.w};
            #pragma unroll
            for (int i = 0; i < 8; i++)
                #pragma unroll
                for (int j = 0; j < 8; j++)
                    acc[i][j] += af[i]*bf[j];
        }
        __syncthreads();
    }

    // fused scale + causal mask + softmax (row reduce over 16-lane group)
    const float scale = 0.0625f;   // 1/sqrt(256)
    #pragma unroll
    for (int i = 0; i < 8; i++) {
        int q = (i < 4) ? (ty*4 + i) : (64 + ty*4 + i - 4);
        float mx = -1e30f;
        #pragma unroll
        for (int j = 0; j < 8; j++) {
            int k = (j < 4) ? (tx*4 + j) : (64 + tx*4 + j - 4);
            float v = (k > q) ? -1e30f : acc[i][j] * scale;
            acc[i][j] = v;
            mx = fmaxf(mx, v);
        }
        #pragma unroll
        for (int s = 8; s > 0; s >>= 1)
            mx = fmaxf(mx, __shfl_xor_sync(0xFFFFFFFF, mx, s));
        float sum = 0.f;
        #pragma unroll
        for (int j = 0; j < 8; j++) {
            float e = __expf(acc[i][j] - mx);
            acc[i][j] = e;
            sum += e;
        }
        #pragma unroll
        for (int s = 8; s > 0; s >>= 1)
            sum += __shfl_xor_sync(0xFFFFFFFF, sum, s);
        float inv = 1.f / sum;
        #pragma unroll
        for (int j = 0; j < 8; j++) {
            int k = (j < 4) ? (tx*4 + j) : (64 + tx*4 + j - 4);
            Wp[q*Tn + k] = acc[i][j] * inv;
        }
    }
}

// ---------------- AV: O[q,d] = sum_k P[q,k] V[k,d] (output tf32-rounded) ----
__global__ void __launch_bounds__(256, 2)
av_k(const float* __restrict__ W, const float* __restrict__ QKV,
     float* __restrict__ Att)
{
    int bh = blockIdx.x;
    int b = bh >> 2, h = bh & 3;
    const float* Wp = W + (size_t)bh*Tn*Tn;
    const float* Vp = QKV + (size_t)b*Tn*768 + 512 + h*HSn;
    float* Op = Att + (size_t)b*Tn*Cn + h*HSn;

    __shared__ float Ps[16][128];
    __shared__ float Vs[16][64];
    int tid = threadIdx.x;
    int tx = tid & 15, ty = tid >> 4;

    float acc[8][4];
    #pragma unroll
    for (int i = 0; i < 8; i++)
        #pragma unroll
        for (int j = 0; j < 4; j++) acc[i][j] = 0.f;

    for (int k0 = 0; k0 < Tn; k0 += 16) {
        #pragma unroll
        for (int it = 0; it < 2; it++) {
            int v  = tid + it*256;
            int q  = v >> 2;
            int f4 = (v & 3) * 4;
            float4 pa = *(const float4*)(Wp + (size_t)q*Tn + k0 + f4);
            Ps[f4+0][q] = pa.x; Ps[f4+1][q] = pa.y;
            Ps[f4+2][q] = pa.z; Ps[f4+3][q] = pa.w;
        }
        {
            int kk = tid >> 4;
            int d4 = (tid & 15) * 4;
            float4 va = *(const float4*)(Vp + (size_t)(k0 + kk)*768 + d4);
            *(float4*)&Vs[kk][d4] = va;
        }
        __syncthreads();
        #pragma unroll
        for (int kk = 0; kk < 16; kk++) {
            float4 a0 = *(float4*)&Ps[kk][ty*4];
            float4 a1 = *(float4*)&Ps[kk][ty*4 + 64];
            float4 b0 = *(float4*)&Vs[kk][tx*4];
            float af[8] = {a0.x,a0.y,a0.z,a0.w,a1.x,a1.y,a1.z,a1.w};
            float bf[4] = {b0.x,b0.y,b0.z,b0.w};
            #pragma unroll
            for (int i = 0; i < 8; i++)
                #pragma unroll
                for (int j = 0; j < 4; j++)
                    acc[i][j] += af[i]*bf[j];
        }
        __syncthreads();
    }

    #pragma unroll
    for (int i = 0; i < 8; i++) {
        int q = (i < 4) ? (ty*4 + i) : (64 + ty*4 + i - 4);
        #pragma unroll
        for (int j = 0; j < 4; j++) {
            int d = tx*4 + j;
            Op[(size_t)q*Cn + d] = roundtf(acc[i][j]);
        }
    }
}

// ---------------- host launcher --------------------------------------------
extern "C" void kernel_launch(void* const* d_in, const int* in_sizes, int n_in,
                              void* d_out, int out_size)
{
    const int*   idx    = (const int*)  d_in[0];
    const float* tok    = (const float*)d_in[1];
    const float* pos    = (const float*)d_in[2];
    const float* ln1_g  = (const float*)d_in[3];
    const float* ln1_b  = (const float*)d_in[4];
    const float* wq     = (const float*)d_in[5];
    const float* wk     = (const float*)d_in[6];
    const float* wv     = (const float*)d_in[7];
    const float* proj_w = (const float*)d_in[8];
    const float* proj_b = (const float*)d_in[9];
    const float* ln2_g  = (const float*)d_in[10];
    const float* ln2_b  = (const float*)d_in[11];
    const float* w1     = (const float*)d_in[12];
    const float* b1     = (const float*)d_in[13];
    const float* w2     = (const float*)d_in[14];
    const float* b2     = (const float*)d_in[15];
    const float* lnf_g  = (const float*)d_in[16];
    const float* lnf_b  = (const float*)d_in[17];
    const float* lm_w   = (const float*)d_in[18];
    const float* lm_b   = (const float*)d_in[19];
    float* out = (float*)d_out;

    float *X, *Hb, *QKV, *Att, *FF, *W, *rW;
    cudaGetSymbolAddress((void**)&X,   g_X);
    cudaGetSymbolAddress((void**)&Hb,  g_Hb);
    cudaGetSymbolAddress((void**)&QKV, g_QKV);
    cudaGetSymbolAddress((void**)&Att, g_Att);
    cudaGetSymbolAddress((void**)&FF,  g_FF);
    cudaGetSymbolAddress((void**)&W,   g_W);
    cudaGetSymbolAddress((void**)&rW,  g_rW);

    // pre-round / pack all weights to tf32 grid
    packqkv_k<<<512, 256>>>(wq, wk, wv, rW + RW_QKV);
    roundw_k<<<512, 256>>>(proj_w, rW + RW_PJ, Ln*Cn*Cn);
    roundw_k<<<512, 256>>>(w1,     rW + RW_W1, Ln*Cn*DFFn);
    roundw_k<<<512, 256>>>(w2,     rW + RW_W2, Ln*DFFn*Cn);
    roundw_k<<<512, 256>>>(lm_w,   rW + RW_LM, Cn*Vn);

    embed_k<<<BT, 256>>>(idx, tok, pos, X);

    dim3 gC(Cn/128, BT/128);      // N=256
    dim3 gQKV(768/128, BT/128);   // N=768
    dim3 gF(DFFn/128, BT/128);    // N=1024
    dim3 gV((Vn + 127)/128, BT/128);

    for (int l = 0; l < Ln; l++) {
        ln_k<<<BT, 256>>>(X, Hb, ln1_g + l*Cn, ln1_b + l*Cn);

        // fused QKV: [BT,256] x [256,768]
        tcgemm_k<0><<<gQKV, 256>>>(BT, 768, Cn, Hb, Cn,
                                   rW + RW_QKV + (size_t)l*Cn*768, 768,
                                   nullptr, nullptr, QKV, 768);

        scores_k<<<Bv*Hn, 256>>>(QKV, W);   // includes causal softmax
        av_k<<<Bv*Hn, 256>>>(W, QKV, Att);

        // x = x + att @ proj_w + proj_b
        tcgemm_k<3><<<gC, 256>>>(BT, Cn, Cn, Att, Cn, rW + RW_PJ + (size_t)l*Cn*Cn, Cn,
                                 proj_b + l*Cn, X, X, Cn);

        ln_k<<<BT, 256>>>(X, Hb, ln2_g + l*Cn, ln2_b + l*Cn);

        // ff = relu(h2 @ w1 + b1)  (rounded to tf32 grid)
        tcgemm_k<13><<<gF, 256>>>(BT, DFFn, Cn, Hb, Cn, rW + RW_W1 + (size_t)l*Cn*DFFn, DFFn,
                                  b1 + l*DFFn, nullptr, FF, DFFn);
        // x = x + ff @ w2 + b2
        tcgemm_k<3><<<gC, 256>>>(BT, Cn, DFFn, FF, DFFn, rW + RW_W2 + (size_t)l*DFFn*Cn, Cn,
                                 b2 + l*Cn, X, X, Cn);
    }

    ln_k<<<BT, 256>>>(X, Hb, lnf_g, lnf_b);
    tcgemm_k<1><<<gV, 256>>>(BT, Vn, Cn, Hb, Cn, rW + RW_LM, Vn,
                             lm_b, nullptr, out, Vn);
}

// round 7
// speedup vs baseline: 2.1663x; 1.1952x over previous
#include <cuda_runtime.h>
#include <math.h>

// Problem constants
#define Bv   128
#define Tn   128
#define Cn   256
#define Hn   4
#define Ln   6
#define Vn   10000
#define HSn  64
#define DFFn 1024
#define BT   (Bv*Tn)   // 16384 rows

// ---------------- scratch (device globals; no allocation allowed) ----------
__device__ float g_X  [BT*Cn];      // residual stream
__device__ float g_Hb [BT*Cn];      // layernorm output (tf32-rounded)
__device__ float g_QKV[BT*768];     // fused QKV output [row][768]
__device__ float g_Att[BT*Cn];      // attention out (tf32-rounded)
__device__ float g_FF [BT*DFFn];    // relu MLP hidden (tf32-rounded)

// pre-rounded (tf32 grid) weights
#define RW_QKV 0                        // packed [L][C][768]
#define RW_PJ  1179648
#define RW_W1  1572864
#define RW_W2  3145728
#define RW_LM  4718592
#define RW_TOT 7278592
__device__ float g_rW [RW_TOT];

// ---------------- helpers ---------------------------------------------------
__device__ __forceinline__ unsigned f2tf32(float x) {
    unsigned r;
    asm("cvt.rna.tf32.f32 %0, %1;" : "=r"(r) : "f"(x));
    return r;
}
__device__ __forceinline__ float roundtf(float x) {
    return __uint_as_float(f2tf32(x));
}

__device__ __forceinline__ void mma_tf32(float* c, const unsigned* a, const unsigned* b) {
    asm volatile(
        "mma.sync.aligned.m16n8k8.row.col.f32.tf32.tf32.f32 "
        "{%0,%1,%2,%3}, {%4,%5,%6,%7}, {%8,%9}, {%0,%1,%2,%3};"
        : "+f"(c[0]), "+f"(c[1]), "+f"(c[2]), "+f"(c[3])
        : "r"(a[0]), "r"(a[1]), "r"(a[2]), "r"(a[3]), "r"(b[0]), "r"(b[1]));
}

__device__ __forceinline__ void cp16(unsigned dst_smem, const void* src) {
    asm volatile("cp.async.cg.shared.global [%0], [%1], 16;"
                 :: "r"(dst_smem), "l"(src));
}
__device__ __forceinline__ void cp16z(unsigned dst_smem, const void* src, int sz) {
    asm volatile("cp.async.cg.shared.global [%0], [%1], 16, %2;"
                 :: "r"(dst_smem), "l"(src), "r"(sz));
}
__device__ __forceinline__ void cp_commit() {
    asm volatile("cp.async.commit_group;" ::);
}
__device__ __forceinline__ void cp_wait0() {
    asm volatile("cp.async.wait_group 0;" ::);
}

// ---------------- weight pre-rounding --------------------------------------
__global__ void roundw_k(const float* __restrict__ in, float* __restrict__ out, int n)
{
    for (int i = blockIdx.x*256 + threadIdx.x; i < n; i += gridDim.x*256)
        out[i] = roundtf(in[i]);
}

// pack wq|wk|wv -> interleaved [L][C][768], tf32-rounded
__global__ void packqkv_k(const float* __restrict__ wq,
                          const float* __restrict__ wk,
                          const float* __restrict__ wv,
                          float* __restrict__ out)
{
    int n = Ln*Cn*768;
    for (int i = blockIdx.x*256 + threadIdx.x; i < n; i += gridDim.x*256) {
        int l = i / (Cn*768);
        int r = i % (Cn*768);
        int c = r / 768;
        int j = r % 768;
        float v;
        int base = l*Cn*Cn + c*Cn;
        if (j < 256)      v = wq[base + j];
        else if (j < 512) v = wk[base + j - 256];
        else              v = wv[base + j - 512];
        out[i] = roundtf(v);
    }
}

// ---------------- embedding ------------------------------------------------
__global__ void embed_k(const int* __restrict__ idx,
                        const float* __restrict__ tok,
                        const float* __restrict__ pos,
                        float* __restrict__ X)
{
    int bt = blockIdx.x;
    int c  = threadIdx.x;
    int t  = bt % Tn;
    int id = idx[bt];
    X[bt*Cn + c] = tok[id*Cn + c] + pos[t*Cn + c];
}

// ---------------- layernorm: one warp per row (no smem, shfl only) ---------
__global__ void ln_k(const float* __restrict__ in, float* __restrict__ out,
                     const float* __restrict__ g, const float* __restrict__ b)
{
    int row  = blockIdx.x * 8 + (threadIdx.x >> 5);
    int lane = threadIdx.x & 31;
    const float* p = in + (size_t)row*Cn;

    float4 a = *(const float4*)(p + lane*4);
    float4 c = *(const float4*)(p + 128 + lane*4);
    float s = a.x+a.y+a.z+a.w + c.x+c.y+c.z+c.w;
    #pragma unroll
    for (int o = 16; o > 0; o >>= 1) s += __shfl_xor_sync(0xFFFFFFFF, s, o);
    float mean = s * (1.0f/Cn);

    float dx0=a.x-mean, dx1=a.y-mean, dx2=a.z-mean, dx3=a.w-mean;
    float dy0=c.x-mean, dy1=c.y-mean, dy2=c.z-mean, dy3=c.w-mean;
    float v = dx0*dx0+dx1*dx1+dx2*dx2+dx3*dx3 + dy0*dy0+dy1*dy1+dy2*dy2+dy3*dy3;
    #pragma unroll
    for (int o = 16; o > 0; o >>= 1) v += __shfl_xor_sync(0xFFFFFFFF, v, o);
    float r = rsqrtf(v * (1.0f/Cn) + 1e-5f);

    float4 ga = *(const float4*)(g + lane*4);
    float4 gc = *(const float4*)(g + 128 + lane*4);
    float4 ba = *(const float4*)(b + lane*4);
    float4 bc = *(const float4*)(b + 128 + lane*4);
    float* q = out + (size_t)row*Cn;
    float4 o1 = make_float4(roundtf(dx0*r*ga.x + ba.x), roundtf(dx1*r*ga.y + ba.y),
                            roundtf(dx2*r*ga.z + ba.z), roundtf(dx3*r*ga.w + ba.w));
    float4 o2 = make_float4(roundtf(dy0*r*gc.x + bc.x), roundtf(dy1*r*gc.y + bc.y),
                            roundtf(dy2*r*gc.z + bc.z), roundtf(dy3*r*gc.w + bc.w));
    *(float4*)(q + lane*4)       = o1;
    *(float4*)(q + 128 + lane*4) = o2;
}

// ---------------- TF32 tensor-core GEMM (cp.async double-buffered) ----------
// EPI bit0 = +bias[n], bit1 = +res, bit2 = relu, bit3 = round output to tf32
template<int EPI>
__global__ void __launch_bounds__(256, 2)
tcgemm_k(int M, int N, int K,
         const float* __restrict__ A, int lda,
         const float* __restrict__ B, int ldb,
         const float* __restrict__ bias,
         const float* __restrict__ res,
         float* __restrict__ C, int ldc)
{
    __shared__ unsigned As[2][128][20];
    __shared__ unsigned Bs[2][16][136];

    int tid  = threadIdx.x;
    int wid  = tid >> 5, lane = tid & 31;
    int grp  = lane >> 2, tg = lane & 3;
    int wm   = (wid & 3) * 32;
    int wn   = (wid >> 2) * 64;
    int bm   = blockIdx.y * 128, bn = blockIdx.x * 128;

    float acc[2][8][4];
    #pragma unroll
    for (int mt = 0; mt < 2; mt++)
        #pragma unroll
        for (int nt = 0; nt < 8; nt++)
            #pragma unroll
            for (int r = 0; r < 4; r++) acc[mt][nt][r] = 0.f;

    int niter = K >> 4;

    {
        #pragma unroll
        for (int it = 0; it < 2; it++) {
            int c = tid + it*256;
            int row = c >> 2, kc = (c & 3) * 4;
            unsigned d = (unsigned)__cvta_generic_to_shared(&As[0][row][kc]);
            cp16(d, A + (size_t)(bm + row)*lda + kc);
        }
        #pragma unroll
        for (int it = 0; it < 2; it++) {
            int c = tid + it*256;
            int kr = c >> 5, nc = (c & 31) * 4;
            unsigned d = (unsigned)__cvta_generic_to_shared(&Bs[0][kr][nc]);
            int col = bn + nc;
            cp16z(d, B + (size_t)kr*ldb + (col < N ? col : 0), col < N ? 16 : 0);
        }
        cp_commit();
    }

    for (int i = 0; i < niter; i++) {
        int s = i & 1;
        cp_wait0();
        __syncthreads();

        if (i + 1 < niter) {
            int k0 = (i + 1) << 4;
            #pragma unroll
            for (int it = 0; it < 2; it++) {
                int c = tid + it*256;
                int row = c >> 2, kc = (c & 3) * 4;
                unsigned d = (unsigned)__cvta_generic_to_shared(&As[s^1][row][kc]);
                cp16(d, A + (size_t)(bm + row)*lda + k0 + kc);
            }
            #pragma unroll
            for (int it = 0; it < 2; it++) {
                int c = tid + it*256;
                int kr = c >> 5, nc = (c & 31) * 4;
                unsigned d = (unsigned)__cvta_generic_to_shared(&Bs[s^1][kr][nc]);
                int col = bn + nc;
                cp16z(d, B + (size_t)(k0 + kr)*ldb + (col < N ? col : 0),
                      col < N ? 16 : 0);
            }
            cp_commit();
        }

        #pragma unroll
        for (int ks = 0; ks < 2; ks++) {
            int k = ks*8;
            unsigned bfr[8][2];
            #pragma unroll
            for (int nt = 0; nt < 8; nt++) {
                bfr[nt][0] = Bs[s][k+tg  ][wn + nt*8 + grp];
                bfr[nt][1] = Bs[s][k+tg+4][wn + nt*8 + grp];
            }
            #pragma unroll
            for (int mt = 0; mt < 2; mt++) {
                unsigned afr[4];
                afr[0] = As[s][wm + mt*16 + grp    ][k + tg    ];
                afr[1] = As[s][wm + mt*16 + grp + 8][k + tg    ];
                afr[2] = As[s][wm + mt*16 + grp    ][k + tg + 4];
                afr[3] = As[s][wm + mt*16 + grp + 8][k + tg + 4];
                #pragma unroll
                for (int nt = 0; nt < 8; nt++)
                    mma_tf32(acc[mt][nt], afr, bfr[nt]);
            }
        }
    }

    #pragma unroll
    for (int mt = 0; mt < 2; mt++) {
        int r0 = bm + wm + mt*16 + grp;
        #pragma unroll
        for (int nt = 0; nt < 8; nt++) {
            int c0 = bn + wn + nt*8 + 2*tg;
            #pragma unroll
            for (int half = 0; half < 2; half++) {
                int r = r0 + half*8;
                float v0 = acc[mt][nt][half*2+0];
                float v1 = acc[mt][nt][half*2+1];
                if (c0 < N) {
                    if (EPI & 1) v0 += bias[c0];
                    if (EPI & 2) v0 += res[(size_t)r*ldc + c0];
                    if (EPI & 4) v0 = fmaxf(v0, 0.f);
                    if (EPI & 8) v0 = roundtf(v0);
                    C[(size_t)r*ldc + c0] = v0;
                }
                if (c0 + 1 < N) {
                    if (EPI & 1) v1 += bias[c0+1];
                    if (EPI & 2) v1 += res[(size_t)r*ldc + c0+1];
                    if (EPI & 4) v1 = fmaxf(v1, 0.f);
                    if (EPI & 8) v1 = roundtf(v1);
                    C[(size_t)r*ldc + c0+1] = v1;
                }
            }
        }
    }
}

// ---------------- fused flash attention (tensor cores) ----------------------
// one block per (b,h); 8 warps; warp w owns score rows [16w, 16w+16).
// S = Q K^T (tf32 mma) -> causal softmax in-register (quad shuffles) ->
// P (tf32, warp-private smem) -> O = P V (tf32 mma) -> Att (rounded).
// smem words: Qs 128*72 | Ks 64*133 | Vs 128*72 | Ps 8*(16*132)
#define ATT_QS   0
#define ATT_KS   9216
#define ATT_VS   17728
#define ATT_PS   26944
#define ATT_WORDS 43840
#define ATT_BYTES (ATT_WORDS*4)

__global__ void __launch_bounds__(256, 1)
attn_k(const float* __restrict__ QKV, float* __restrict__ Att)
{
    extern __shared__ unsigned sm[];
    unsigned* smQ = sm + ATT_QS;
    unsigned* smK = sm + ATT_KS;
    unsigned* smV = sm + ATT_VS;

    int bh = blockIdx.x;
    int b = bh >> 2, h = bh & 3;
    const float* Qp = QKV + (size_t)b*Tn*768 + h*HSn;
    const float* Kp = Qp + 256;
    const float* Vp = Qp + 512;

    int tid = threadIdx.x;
    int wid = tid >> 5, lane = tid & 31;
    int grp = lane >> 2, tg = lane & 3;
    int wm  = wid * 16;

    // ---- load Q,K,V tiles (tf32-rounded); K stored transposed [d][kk] ----
    #pragma unroll
    for (int it = 0; it < 8; it++) {
        int c = tid + it*256;          // 0..2047 float4 chunks
        int row = c >> 4;              // 0..127
        int f   = (c & 15) * 4;        // 0..60
        const float* src = Qp + (size_t)row*768 + f;
        float4 qa = *(const float4*)(src);
        smQ[row*72 + f+0] = f2tf32(qa.x); smQ[row*72 + f+1] = f2tf32(qa.y);
        smQ[row*72 + f+2] = f2tf32(qa.z); smQ[row*72 + f+3] = f2tf32(qa.w);
        float4 ka = *(const float4*)(src + 256);
        smK[(f+0)*133 + row] = f2tf32(ka.x); smK[(f+1)*133 + row] = f2tf32(ka.y);
        smK[(f+2)*133 + row] = f2tf32(ka.z); smK[(f+3)*133 + row] = f2tf32(ka.w);
        float4 va = *(const float4*)(src + 512);
        smV[row*72 + f+0] = f2tf32(va.x); smV[row*72 + f+1] = f2tf32(va.y);
        smV[row*72 + f+2] = f2tf32(va.z); smV[row*72 + f+3] = f2tf32(va.w);
    }
    __syncthreads();

    // ---- S = Q K^T : warp tile 16x128, K-dim 64 ----
    float sacc[16][4];
    #pragma unroll
    for (int nt = 0; nt < 16; nt++)
        #pragma unroll
        for (int r = 0; r < 4; r++) sacc[nt][r] = 0.f;

    #pragma unroll
    for (int k0 = 0; k0 < HSn; k0 += 8) {
        unsigned aq[4];
        aq[0] = smQ[(wm+grp  )*72 + k0+tg  ];
        aq[1] = smQ[(wm+grp+8)*72 + k0+tg  ];
        aq[2] = smQ[(wm+grp  )*72 + k0+tg+4];
        aq[3] = smQ[(wm+grp+8)*72 + k0+tg+4];
        #pragma unroll
        for (int nt = 0; nt < 16; nt++) {
            unsigned bk[2];
            bk[0] = smK[(k0+tg  )*133 + nt*8+grp];
            bk[1] = smK[(k0+tg+4)*133 + nt*8+grp];
            mma_tf32(sacc[nt], aq, bk);
        }
    }

    // ---- causal softmax per row (rows grp / grp+8; quad shuffles) ----
    const float scale = 0.0625f;   // 1/sqrt(256)
    unsigned* Pw = sm + ATT_PS + wid*(16*132);
    #pragma unroll
    for (int r = 0; r < 2; r++) {
        int q = wm + grp + 8*r;
        float mx = -1e30f;
        #pragma unroll
        for (int nt = 0; nt < 16; nt++) {
            int col = nt*8 + 2*tg;
            float v0 = (col   > q) ? -1e30f : sacc[nt][2*r]   * scale;
            float v1 = (col+1 > q) ? -1e30f : sacc[nt][2*r+1] * scale;
            sacc[nt][2*r] = v0; sacc[nt][2*r+1] = v1;
            mx = fmaxf(mx, fmaxf(v0, v1));
        }
        mx = fmaxf(mx, __shfl_xor_sync(0xFFFFFFFF, mx, 1));
        mx = fmaxf(mx, __shfl_xor_sync(0xFFFFFFFF, mx, 2));
        float sum = 0.f;
        #pragma unroll
        for (int nt = 0; nt < 16; nt++) {
            float e0 = __expf(sacc[nt][2*r]   - mx);
            float e1 = __expf(sacc[nt][2*r+1] - mx);
            sacc[nt][2*r] = e0; sacc[nt][2*r+1] = e1;
            sum += e0 + e1;
        }
        sum += __shfl_xor_sync(0xFFFFFFFF, sum, 1);
        sum += __shfl_xor_sync(0xFFFFFFFF, sum, 2);
        float inv = 1.f / sum;
        #pragma unroll
        for (int nt = 0; nt < 16; nt++) {
            uint2 st;
            st.x = f2tf32(sacc[nt][2*r]   * inv);
            st.y = f2tf32(sacc[nt][2*r+1] * inv);
            *(uint2*)&Pw[(grp + 8*r)*132 + nt*8 + 2*tg] = st;
        }
    }
    __syncwarp();

    // ---- O = P V : warp tile 16x64, K-dim 128 ----
    float oacc[8][4];
    #pragma unroll
    for (int nt = 0; nt < 8; nt++)
        #pragma unroll
        for (int r = 0; r < 4; r++) oacc[nt][r] = 0.f;

    #pragma unroll
    for (int k0 = 0; k0 < Tn; k0 += 8) {
        unsigned ap[4];
        ap[0] = Pw[(grp  )*132 + k0+tg  ];
        ap[1] = Pw[(grp+8)*132 + k0+tg  ];
        ap[2] = Pw[(grp  )*132 + k0+tg+4];
        ap[3] = Pw[(grp+8)*132 + k0+tg+4];
        #pragma unroll
        for (int nt = 0; nt < 8; nt++) {
            unsigned bv[2];
            bv[0] = smV[(k0+tg  )*72 + nt*8+grp];
            bv[1] = smV[(k0+tg+4)*72 + nt*8+grp];
            mma_tf32(oacc[nt], ap, bv);
        }
    }

    // ---- write O (tf32-rounded) ----
    float* Op = Att + (size_t)b*Tn*Cn + h*HSn;
    #pragma unroll
    for (int nt = 0; nt < 8; nt++) {
        int col = nt*8 + 2*tg;
        #pragma unroll
        for (int r = 0; r < 2; r++) {
            int q = wm + grp + 8*r;
            float2 o;
            o.x = roundtf(oacc[nt][2*r]);
            o.y = roundtf(oacc[nt][2*r+1]);
            *(float2*)(Op + (size_t)q*Cn + col) = o;
        }
    }
}

// ---------------- host launcher --------------------------------------------
extern "C" void kernel_launch(void* const* d_in, const int* in_sizes, int n_in,
                              void* d_out, int out_size)
{
    const int*   idx    = (const int*)  d_in[0];
    const float* tok    = (const float*)d_in[1];
    const float* pos    = (const float*)d_in[2];
    const float* ln1_g  = (const float*)d_in[3];
    const float* ln1_b  = (const float*)d_in[4];
    const float* wq     = (const float*)d_in[5];
    const float* wk     = (const float*)d_in[6];
    const float* wv     = (const float*)d_in[7];
    const float* proj_w = (const float*)d_in[8];
    const float* proj_b = (const float*)d_in[9];
    const float* ln2_g  = (const float*)d_in[10];
    const float* ln2_b  = (const float*)d_in[11];
    const float* w1     = (const float*)d_in[12];
    const float* b1     = (const float*)d_in[13];
    const float* w2     = (const float*)d_in[14];
    const float* b2     = (const float*)d_in[15];
    const float* lnf_g  = (const float*)d_in[16];
    const float* lnf_b  = (const float*)d_in[17];
    const float* lm_w   = (const float*)d_in[18];
    const float* lm_b   = (const float*)d_in[19];
    float* out = (float*)d_out;

    float *X, *Hb, *QKV, *Att, *FF, *rW;
    cudaGetSymbolAddress((void**)&X,   g_X);
    cudaGetSymbolAddress((void**)&Hb,  g_Hb);
    cudaGetSymbolAddress((void**)&QKV, g_QKV);
    cudaGetSymbolAddress((void**)&Att, g_Att);
    cudaGetSymbolAddress((void**)&FF,  g_FF);
    cudaGetSymbolAddress((void**)&rW,  g_rW);

    cudaFuncSetAttribute(attn_k, cudaFuncAttributeMaxDynamicSharedMemorySize,
                         ATT_BYTES);

    // pre-round / pack all weights to tf32 grid
    packqkv_k<<<512, 256>>>(wq, wk, wv, rW + RW_QKV);
    roundw_k<<<512, 256>>>(proj_w, rW + RW_PJ, Ln*Cn*Cn);
    roundw_k<<<512, 256>>>(w1,     rW + RW_W1, Ln*Cn*DFFn);
    roundw_k<<<512, 256>>>(w2,     rW + RW_W2, Ln*DFFn*Cn);
    roundw_k<<<512, 256>>>(lm_w,   rW + RW_LM, Cn*Vn);

    embed_k<<<BT, 256>>>(idx, tok, pos, X);

    dim3 gC(Cn/128, BT/128);      // N=256
    dim3 gQKV(768/128, BT/128);   // N=768
    dim3 gF(DFFn/128, BT/128);    // N=1024
    dim3 gV((Vn + 127)/128, BT/128);

    for (int l = 0; l < Ln; l++) {
        ln_k<<<BT/8, 256>>>(X, Hb, ln1_g + l*Cn, ln1_b + l*Cn);

        // fused QKV: [BT,256] x [256,768]
        tcgemm_k<0><<<gQKV, 256>>>(BT, 768, Cn, Hb, Cn,
                                   rW + RW_QKV + (size_t)l*Cn*768, 768,
                                   nullptr, nullptr, QKV, 768);

        attn_k<<<Bv*Hn, 256, ATT_BYTES>>>(QKV, Att);

        // x = x + att @ proj_w + proj_b
        tcgemm_k<3><<<gC, 256>>>(BT, Cn, Cn, Att, Cn, rW + RW_PJ + (size_t)l*Cn*Cn, Cn,
                                 proj_b + l*Cn, X, X, Cn);

        ln_k<<<BT/8, 256>>>(X, Hb, ln2_g + l*Cn, ln2_b + l*Cn);

        // ff = relu(h2 @ w1 + b1)  (rounded to tf32 grid)
        tcgemm_k<13><<<gF, 256>>>(BT, DFFn, Cn, Hb, Cn, rW + RW_W1 + (size_t)l*Cn*DFFn, DFFn,
                                  b1 + l*DFFn, nullptr, FF, DFFn);
        // x = x + ff @ w2 + b2
        tcgemm_k<3><<<gC, 256>>>(BT, Cn, DFFn, FF, DFFn, rW + RW_W2 + (size_t)l*DFFn*Cn, Cn,
                                 b2 + l*Cn, X, X, Cn);
    }

    ln_k<<<BT/8, 256>>>(X, Hb, lnf_g, lnf_b);
    tcgemm_k<1><<<gV, 256>>>(BT, Vn, Cn, Hb, Cn, rW + RW_LM, Vn,
                             lm_b, nullptr, out, Vn);
}